// round 2
// baseline (speedup 1.0000x reference)
#include <cuda_runtime.h>
#include <cstdint>
#include <cstddef>

#define BB 32
#define N1 2048
#define S1 512
#define S2 256
#define NS 32
#define R2C 0.25f
#define NSLOT 64
#define CMAX 256

// ---------------- static device buffers (no allocation allowed) ----------------
__device__ float g_F0[(size_t)BB*64*N1];        // conv1 raw
__device__ float g_F1[(size_t)BB*64*N1];        // conv2 raw
__device__ float g_nx1[(size_t)BB*S1*3];
__device__ int   g_fps1[BB*S1];
__device__ int   g_gi1[(size_t)BB*S1*NS];
__device__ float g_G1[(size_t)BB*S1*128*NS];    // sg1a raw (256MB)
__device__ float g_F1max[(size_t)BB*S1*128];
__device__ float g_nx2[(size_t)BB*S2*3];
__device__ int   g_fps2[BB*S2];
__device__ int   g_gi2[(size_t)BB*S2*NS];
__device__ float g_G2[(size_t)BB*S2*256*NS];    // sg2a raw (256MB)
__device__ float g_F2max[(size_t)BB*S2*256];

__device__ double g_psum[6*NSLOT*CMAX];
__device__ double g_psq [6*NSLOT*CMAX];
__device__ float  g_scale[6*CMAX];
__device__ float  g_bias [6*CMAX];

// ---------------- BN finalize ----------------
__global__ void k_fin(const double* __restrict__ psum, const double* __restrict__ psq,
                      float* __restrict__ sc, float* __restrict__ bi, int C, double invM)
{
    int t = threadIdx.x;
    if (t >= C) return;
    double s = 0.0, q = 0.0;
    for (int k = 0; k < NSLOT; k++) { s += psum[k*CMAX + t]; q += psq[k*CMAX + t]; }
    double mean = s * invM;
    double var  = q * invM - mean * mean;
    if (var < 0.0) var = 0.0;
    double sv = 1.0 / sqrt(var + 1e-5);
    sc[t] = (float)sv;
    bi[t] = (float)(-mean * sv);
}

// ---------------- conv1: [64,3] x [B,3,N] ----------------
__global__ void k_conv1(const float* __restrict__ x, const float* __restrict__ W,
                        float* __restrict__ F0, double* __restrict__ psum, double* __restrict__ psq)
{
    int c = blockIdx.x, b = blockIdx.y, t = threadIdx.x;
    float w0 = W[c*3], w1 = W[c*3+1], w2 = W[c*3+2];
    const float* xb = x + (size_t)b*3*N1;
    float* o = F0 + ((size_t)b*64 + c)*N1;
    float ls = 0.f, lq = 0.f;
    for (int n = t; n < N1; n += 256) {
        float v = w0*xb[n] + w1*xb[N1+n] + w2*xb[2*N1+n];
        o[n] = v; ls += v; lq += v*v;
    }
    for (int off = 16; off; off >>= 1) {
        ls += __shfl_down_sync(0xffffffffu, ls, off);
        lq += __shfl_down_sync(0xffffffffu, lq, off);
    }
    __shared__ float ws_[8], wq_[8];
    if ((t & 31) == 0) { ws_[t >> 5] = ls; wq_[t >> 5] = lq; }
    __syncthreads();
    if (t == 0) {
        float S = 0.f, Q = 0.f;
        for (int i = 0; i < 8; i++) { S += ws_[i]; Q += wq_[i]; }
        atomicAdd(&psum[(b & (NSLOT-1))*CMAX + c], (double)S);
        atomicAdd(&psq [(b & (NSLOT-1))*CMAX + c], (double)Q);
    }
}

// ---------------- conv2: [64,64] x relu(bn(F0)) ----------------
__global__ void k_conv2(const float* __restrict__ F0, const float* __restrict__ W,
                        const float* __restrict__ sc0, const float* __restrict__ bi0,
                        float* __restrict__ F1, double* __restrict__ psum, double* __restrict__ psq)
{
    __shared__ float in_t[64*64];
    __shared__ float ws[64*65];
    __shared__ float pspart[4*64], pqpart[4*64];
    int tile = blockIdx.x, b = blockIdx.y, t = threadIdx.x;
    for (int i = t; i < 4096; i += 256) { int c = i >> 6, k = i & 63; ws[c*65 + k] = W[i]; }
    const float* F0b = F0 + (size_t)b*64*N1 + tile*64;
    for (int i = t; i < 4096; i += 256) {
        int k = i >> 6, nn = i & 63;
        float v = F0b[(size_t)k*N1 + nn]*sc0[k] + bi0[k];
        in_t[k*64 + nn] = fmaxf(v, 0.f);
    }
    __syncthreads();
    int c = t & 63, nq = t >> 6;
    float acc[16];
    #pragma unroll
    for (int j = 0; j < 16; j++) acc[j] = 0.f;
    for (int k = 0; k < 64; k++) {
        float wv = ws[c*65 + k];
        const float* ar = &in_t[k*64 + nq*16];
        #pragma unroll
        for (int jq = 0; jq < 4; jq++) {
            float4 a = *(const float4*)(ar + 4*jq);
            acc[4*jq+0] += wv*a.x; acc[4*jq+1] += wv*a.y;
            acc[4*jq+2] += wv*a.z; acc[4*jq+3] += wv*a.w;
        }
    }
    float lsum = 0.f, lsq = 0.f;
    float* F1b = F1 + ((size_t)b*64 + c)*N1 + tile*64 + nq*16;
    #pragma unroll
    for (int j = 0; j < 16; j++) { float v = acc[j]; F1b[j] = v; lsum += v; lsq += v*v; }
    pspart[nq*64 + c] = lsum; pqpart[nq*64 + c] = lsq;
    __syncthreads();
    if (t < 64) {
        float s = pspart[t] + pspart[64+t] + pspart[128+t] + pspart[192+t];
        float q = pqpart[t] + pqpart[64+t] + pqpart[128+t] + pqpart[192+t];
        int slot = (blockIdx.x + 32*blockIdx.y) & (NSLOT-1);
        atomicAdd(&psum[slot*CMAX + t], (double)s);
        atomicAdd(&psq [slot*CMAX + t], (double)q);
    }
}

// ---------------- FPS (exact fp match with reference) ----------------
template<int N, int S>
__global__ void k_fps(const float* __restrict__ P, size_t bstride, size_t pstride, size_t cstride,
                      int* __restrict__ outIdx, float* __restrict__ outXYZ)
{
    int b = blockIdx.x, t = threadIdx.x;
    const float* Pb = P + (size_t)b*bstride;
    __shared__ float dist[N];
    __shared__ float rv[256];
    __shared__ int   ri[256];
    __shared__ int   sfar;
    for (int j = t; j < N; j += 256) dist[j] = 1e10f;
    if (t == 0) sfar = 0;
    __syncthreads();
    for (int s = 0; s < S; s++) {
        int far = sfar;
        float fx = Pb[(size_t)far*pstride];
        float fy = Pb[(size_t)far*pstride + cstride];
        float fz = Pb[(size_t)far*pstride + 2*cstride];
        if (t == 0) {
            outIdx[(size_t)b*S + s] = far;
            float* o = &outXYZ[((size_t)b*S + s)*3];
            o[0] = fx; o[1] = fy; o[2] = fz;
        }
        float bv = -1.f; int bi = N;
        for (int j = t; j < N; j += 256) {
            float dx = __fsub_rn(Pb[(size_t)j*pstride], fx);
            float dy = __fsub_rn(Pb[(size_t)j*pstride + cstride], fy);
            float dz = __fsub_rn(Pb[(size_t)j*pstride + 2*cstride], fz);
            float d = __fadd_rn(__fadd_rn(__fmul_rn(dx,dx), __fmul_rn(dy,dy)), __fmul_rn(dz,dz));
            float nd = fminf(dist[j], d);
            dist[j] = nd;
            if (nd > bv) { bv = nd; bi = j; }
        }
        rv[t] = bv; ri[t] = bi;
        __syncthreads();
        for (int off = 128; off > 0; off >>= 1) {
            if (t < off) {
                float v2 = rv[t+off]; int i2 = ri[t+off];
                if (v2 > rv[t] || (v2 == rv[t] && i2 < ri[t])) { rv[t] = v2; ri[t] = i2; }
            }
            __syncthreads();
        }
        if (t == 0) sfar = ri[0];
        __syncthreads();
    }
}

// ---------------- ball query: first NS ascending indices with d<=R2 ----------------
__global__ void k_ball(const float* __restrict__ C, size_t bstrideC, size_t pstride, size_t cstride,
                       int N, const float* __restrict__ Q, int S, int* __restrict__ gi)
{
    int wid = threadIdx.x >> 5, lane = threadIdx.x & 31;
    int g = blockIdx.x*4 + wid;
    int b = g / S;
    const float* Cb = C + (size_t)b*bstrideC;
    const float* q = Q + (size_t)g*3;
    float qx = q[0], qy = q[1], qz = q[2];
    __shared__ int buf[4][NS];
    int cnt = 0;
    for (int base = 0; base < N && cnt < NS; base += 32) {
        int j = base + lane;
        float dx = __fsub_rn(Cb[(size_t)j*pstride], qx);
        float dy = __fsub_rn(Cb[(size_t)j*pstride + cstride], qy);
        float dz = __fsub_rn(Cb[(size_t)j*pstride + 2*cstride], qz);
        float d = __fadd_rn(__fadd_rn(__fmul_rn(dx,dx), __fmul_rn(dy,dy)), __fmul_rn(dz,dz));
        bool ok = !(d > R2C);
        unsigned m = __ballot_sync(0xffffffffu, ok);
        int pos = cnt + __popc(m & ((1u << lane) - 1u));
        if (ok && pos < NS) buf[wid][pos] = j;
        cnt += __popc(m);
    }
    __syncwarp();
    int first = buf[wid][0];
    int mm = cnt < NS ? cnt : NS;
    int v = (lane < mm) ? buf[wid][lane] : first;
    gi[(size_t)g*NS + lane] = v;
}

// ---------------- SG "a": gather + center/concat + GEMM, store raw + sums ----------------
template<int CIN, int COUT>
__global__ void k_sg_gather(const float* __restrict__ W,
                            const float* __restrict__ Fsrc, size_t sb, size_t sn, size_t sc,
                            const float* __restrict__ fscale, const float* __restrict__ fbias,
                            const int* __restrict__ gi, const int* __restrict__ fpsidx, int S,
                            float* __restrict__ G,
                            double* __restrict__ psum, double* __restrict__ psq)
{
    constexpr int CH = CIN/2;
    constexpr int WPAD = COUT + 4;
    extern __shared__ float sm[];
    float* agg = sm;                         // CIN*NS
    float* wT  = agg + CIN*NS;               // 32*WPAD
    float* fc  = wT + 32*WPAD;               // CH
    float* ps  = fc + CH;                    // 4*COUT
    float* pq  = ps + 4*COUT;                // 4*COUT
    int*   gix = (int*)(pq + 4*COUT);        // 32

    int g = blockIdx.x;
    int b = g / S, s = g % S;
    int t = threadIdx.x;                     // COUT threads
    const float* Fb = Fsrc + (size_t)b*sb;

    if (t < 32) gix[t] = gi[(size_t)g*NS + t];
    if (t < CH) {
        int ci = fpsidx[(size_t)b*S + s];
        float v = Fb[(size_t)ci*sn + (size_t)t*sc]*fscale[t] + fbias[t];
        fc[t] = fmaxf(v, 0.f);
    }
    __syncthreads();
    for (int i = t; i < CH*NS; i += COUT) {
        int c = i % CH, k = i / CH;
        int idx = gix[k];
        float v = Fb[(size_t)idx*sn + (size_t)c*sc]*fscale[c] + fbias[c];
        v = fmaxf(v, 0.f);
        agg[c*NS + k]      = v - fc[c];
        agg[(c+CH)*NS + k] = fc[c];
    }

    constexpr int NC4 = COUT/4;
    int c4 = (t % NC4)*4;
    int sq = t / NC4;
    float acc[4][8];
    #pragma unroll
    for (int a = 0; a < 4; a++)
        #pragma unroll
        for (int c2 = 0; c2 < 8; c2++) acc[a][c2] = 0.f;

    for (int ch = 0; ch < CIN/32; ch++) {
        __syncthreads();
        for (int i = t; i < COUT*32; i += COUT) {
            int c = i >> 5, kk = i & 31;
            wT[kk*WPAD + c] = W[(size_t)c*CIN + ch*32 + kk];
        }
        __syncthreads();
        #pragma unroll
        for (int kk = 0; kk < 32; kk++) {
            float4 wv = *(const float4*)&wT[kk*WPAD + c4];
            float4 a0 = *(const float4*)&agg[(ch*32+kk)*NS + sq*8];
            float4 a1 = *(const float4*)&agg[(ch*32+kk)*NS + sq*8 + 4];
            float w4[4] = {wv.x, wv.y, wv.z, wv.w};
            float av[8] = {a0.x, a0.y, a0.z, a0.w, a1.x, a1.y, a1.z, a1.w};
            #pragma unroll
            for (int ci = 0; ci < 4; ci++)
                #pragma unroll
                for (int sj = 0; sj < 8; sj++)
                    acc[ci][sj] += w4[ci]*av[sj];
        }
    }

    float* Gg = G + (size_t)g*COUT*NS;
    #pragma unroll
    for (int ci = 0; ci < 4; ci++) {
        int row = c4 + ci;
        float lsum = 0.f, lsq = 0.f;
        #pragma unroll
        for (int sj = 0; sj < 8; sj++) { float v = acc[ci][sj]; lsum += v; lsq += v*v; }
        *(float4*)&Gg[row*NS + sq*8]     = make_float4(acc[ci][0], acc[ci][1], acc[ci][2], acc[ci][3]);
        *(float4*)&Gg[row*NS + sq*8 + 4] = make_float4(acc[ci][4], acc[ci][5], acc[ci][6], acc[ci][7]);
        ps[sq*COUT + row] = lsum; pq[sq*COUT + row] = lsq;
    }
    __syncthreads();
    float s0 = ps[t] + ps[COUT+t] + ps[2*COUT+t] + ps[3*COUT+t];
    float q0 = pq[t] + pq[COUT+t] + pq[2*COUT+t] + pq[3*COUT+t];
    int slot = g & (NSLOT-1);
    atomicAdd(&psum[slot*CMAX + t], (double)s0);
    atomicAdd(&psq [slot*CMAX + t], (double)q0);
}

// ---------------- SG "b": bn+relu input, GEMM, row-max + sums only ----------------
template<int C>
__global__ void k_sg_bngemm(const float* __restrict__ W, const float* __restrict__ Graw,
                            const float* __restrict__ insc, const float* __restrict__ inb,
                            float* __restrict__ Fmax,
                            double* __restrict__ psum, double* __restrict__ psq)
{
    constexpr int WPAD = C + 4;
    extern __shared__ float sm[];
    float* agg = sm;                 // C*NS
    float* wT  = agg + C*NS;         // 32*WPAD
    float* ps  = wT + 32*WPAD;       // 4*C
    float* pq  = ps + 4*C;           // 4*C
    float* pm  = pq + 4*C;           // 4*C

    int g = blockIdx.x, t = threadIdx.x;    // C threads
    const float* Gg = Graw + (size_t)g*C*NS;
    for (int i = t; i < C*NS; i += C) {
        int c = i >> 5;
        float v = Gg[i]*insc[c] + inb[c];
        agg[i] = fmaxf(v, 0.f);
    }

    constexpr int NC4 = C/4;
    int c4 = (t % NC4)*4;
    int sq = t / NC4;
    float acc[4][8];
    #pragma unroll
    for (int a = 0; a < 4; a++)
        #pragma unroll
        for (int c2 = 0; c2 < 8; c2++) acc[a][c2] = 0.f;

    for (int ch = 0; ch < C/32; ch++) {
        __syncthreads();
        for (int i = t; i < C*32; i += C) {
            int c = i >> 5, kk = i & 31;
            wT[kk*WPAD + c] = W[(size_t)c*C + ch*32 + kk];
        }
        __syncthreads();
        #pragma unroll
        for (int kk = 0; kk < 32; kk++) {
            float4 wv = *(const float4*)&wT[kk*WPAD + c4];
            float4 a0 = *(const float4*)&agg[(ch*32+kk)*NS + sq*8];
            float4 a1 = *(const float4*)&agg[(ch*32+kk)*NS + sq*8 + 4];
            float w4[4] = {wv.x, wv.y, wv.z, wv.w};
            float av[8] = {a0.x, a0.y, a0.z, a0.w, a1.x, a1.y, a1.z, a1.w};
            #pragma unroll
            for (int ci = 0; ci < 4; ci++)
                #pragma unroll
                for (int sj = 0; sj < 8; sj++)
                    acc[ci][sj] += w4[ci]*av[sj];
        }
    }

    #pragma unroll
    for (int ci = 0; ci < 4; ci++) {
        int row = c4 + ci;
        float lsum = 0.f, lsq = 0.f, lmax = -3.4e38f;
        #pragma unroll
        for (int sj = 0; sj < 8; sj++) {
            float v = acc[ci][sj];
            lsum += v; lsq += v*v; lmax = fmaxf(lmax, v);
        }
        ps[sq*C + row] = lsum; pq[sq*C + row] = lsq; pm[sq*C + row] = lmax;
    }
    __syncthreads();
    float s0 = ps[t] + ps[C+t] + ps[2*C+t] + ps[3*C+t];
    float q0 = pq[t] + pq[C+t] + pq[2*C+t] + pq[3*C+t];
    float m0 = fmaxf(fmaxf(pm[t], pm[C+t]), fmaxf(pm[2*C+t], pm[3*C+t]));
    Fmax[(size_t)g*C + t] = m0;
    int slot = g & (NSLOT-1);
    atomicAdd(&psum[slot*CMAX + t], (double)s0);
    atomicAdd(&psq [slot*CMAX + t], (double)q0);
}

// ---------------- final output f2 ----------------
__global__ void k_out_f2(const float* __restrict__ Fmax, const float* __restrict__ sc,
                         const float* __restrict__ bi, float* __restrict__ out)
{
    size_t i = (size_t)blockIdx.x*256 + threadIdx.x;   // 32*256*256
    int s = i & 255;
    size_t r = i >> 8;
    int c = r & 255;
    int b = (int)(r >> 8);
    float v = Fmax[((size_t)(b*256 + s))*256 + c]*sc[c] + bi[c];
    out[24576 + i] = fmaxf(v, 0.f);
}

// ---------------- launch ----------------
extern "C" void kernel_launch(void* const* d_in, const int* in_sizes, int n_in,
                              void* d_out, int out_size)
{
    const float* x  = (const float*)d_in[0];
    const float* w1 = (const float*)d_in[1];
    const float* w2 = (const float*)d_in[2];
    const float* wa = (const float*)d_in[3];
    const float* wb = (const float*)d_in[4];
    const float* wc = (const float*)d_in[5];
    const float* wd = (const float*)d_in[6];

    void *pF0, *pF1, *pnx1, *pfps1, *pgi1, *pG1, *pF1max;
    void *pnx2, *pfps2, *pgi2, *pG2, *pF2max, *ppsum, *ppsq, *pscale, *pbias;
    cudaGetSymbolAddress(&pF0, g_F0);       cudaGetSymbolAddress(&pF1, g_F1);
    cudaGetSymbolAddress(&pnx1, g_nx1);     cudaGetSymbolAddress(&pfps1, g_fps1);
    cudaGetSymbolAddress(&pgi1, g_gi1);     cudaGetSymbolAddress(&pG1, g_G1);
    cudaGetSymbolAddress(&pF1max, g_F1max); cudaGetSymbolAddress(&pnx2, g_nx2);
    cudaGetSymbolAddress(&pfps2, g_fps2);   cudaGetSymbolAddress(&pgi2, g_gi2);
    cudaGetSymbolAddress(&pG2, g_G2);       cudaGetSymbolAddress(&pF2max, g_F2max);
    cudaGetSymbolAddress(&ppsum, g_psum);   cudaGetSymbolAddress(&ppsq, g_psq);
    cudaGetSymbolAddress(&pscale, g_scale); cudaGetSymbolAddress(&pbias, g_bias);

    double* psum = (double*)ppsum;
    double* psq  = (double*)ppsq;
    float* scl   = (float*)pscale;
    float* bia   = (float*)pbias;

    const int smA1 = (128*NS + 32*(128+4) + 64  + 8*128)*4 + 32*4;
    const int smA2 = (256*NS + 32*(256+4) + 128 + 8*256)*4 + 32*4;
    const int smB1 = (128*NS + 32*(128+4) + 12*128)*4;
    const int smB2 = (256*NS + 32*(256+4) + 12*256)*4;
    cudaFuncSetAttribute(k_sg_gather<256,256>, cudaFuncAttributeMaxDynamicSharedMemorySize, smA2);
    cudaFuncSetAttribute(k_sg_bngemm<256>,     cudaFuncAttributeMaxDynamicSharedMemorySize, smB2);

    cudaMemsetAsync(psum, 0, 6*NSLOT*CMAX*sizeof(double), 0);
    cudaMemsetAsync(psq,  0, 6*NSLOT*CMAX*sizeof(double), 0);

    // stage 0: convs + BN
    k_conv1<<<dim3(64,BB), 256>>>(x, w1, (float*)pF0, psum + 0*NSLOT*CMAX, psq + 0*NSLOT*CMAX);
    k_fin<<<1,64>>>(psum + 0*NSLOT*CMAX, psq + 0*NSLOT*CMAX, scl + 0*CMAX, bia + 0*CMAX, 64, 1.0/((double)BB*N1));
    k_conv2<<<dim3(32,BB), 256>>>((const float*)pF0, w2, scl + 0*CMAX, bia + 0*CMAX,
                                  (float*)pF1, psum + 1*NSLOT*CMAX, psq + 1*NSLOT*CMAX);
    k_fin<<<1,64>>>(psum + 1*NSLOT*CMAX, psq + 1*NSLOT*CMAX, scl + 1*CMAX, bia + 1*CMAX, 64, 1.0/((double)BB*N1));

    // stage 1: FPS + ball on raw coords
    k_fps<N1,S1><<<BB,256>>>(x, (size_t)3*N1, 1, N1, (int*)pfps1, (float*)pnx1);
    k_ball<<<BB*S1/4,128>>>(x, (size_t)3*N1, 1, N1, N1, (const float*)pnx1, S1, (int*)pgi1);

    // sg1
    k_sg_gather<128,128><<<BB*S1, 128, smA1>>>(wa, (const float*)pF1, (size_t)64*N1, 1, N1,
        scl + 1*CMAX, bia + 1*CMAX, (const int*)pgi1, (const int*)pfps1, S1,
        (float*)pG1, psum + 2*NSLOT*CMAX, psq + 2*NSLOT*CMAX);
    k_fin<<<1,128>>>(psum + 2*NSLOT*CMAX, psq + 2*NSLOT*CMAX, scl + 2*CMAX, bia + 2*CMAX, 128, 1.0/((double)BB*S1*NS));
    k_sg_bngemm<128><<<BB*S1, 128, smB1>>>(wb, (const float*)pG1, scl + 2*CMAX, bia + 2*CMAX,
        (float*)pF1max, psum + 3*NSLOT*CMAX, psq + 3*NSLOT*CMAX);
    k_fin<<<1,128>>>(psum + 3*NSLOT*CMAX, psq + 3*NSLOT*CMAX, scl + 3*CMAX, bia + 3*CMAX, 128, 1.0/((double)BB*S1*NS));

    // stage 2: FPS + ball on sampled coords
    k_fps<S1,S2><<<BB,256>>>((const float*)pnx1, (size_t)S1*3, 3, 1, (int*)pfps2, (float*)pnx2);
    k_ball<<<BB*S2/4,128>>>((const float*)pnx1, (size_t)S1*3, 3, 1, S1, (const float*)pnx2, S2, (int*)pgi2);

    // sg2
    k_sg_gather<256,256><<<BB*S2, 256, smA2>>>(wc, (const float*)pF1max, (size_t)S1*128, 128, 1,
        scl + 3*CMAX, bia + 3*CMAX, (const int*)pgi2, (const int*)pfps2, S2,
        (float*)pG2, psum + 4*NSLOT*CMAX, psq + 4*NSLOT*CMAX);
    k_fin<<<1,256>>>(psum + 4*NSLOT*CMAX, psq + 4*NSLOT*CMAX, scl + 4*CMAX, bia + 4*CMAX, 256, 1.0/((double)BB*S2*NS));
    k_sg_bngemm<256><<<BB*S2, 256, smB2>>>(wd, (const float*)pG2, scl + 4*CMAX, bia + 4*CMAX,
        (float*)pF2max, psum + 5*NSLOT*CMAX, psq + 5*NSLOT*CMAX);
    k_fin<<<1,256>>>(psum + 5*NSLOT*CMAX, psq + 5*NSLOT*CMAX, scl + 5*CMAX, bia + 5*CMAX, 256, 1.0/((double)BB*S2*NS));

    // outputs: coords then f2
    cudaMemcpyAsync(d_out, pnx2, (size_t)BB*S2*3*sizeof(float), cudaMemcpyDeviceToDevice, 0);
    k_out_f2<<<(BB*256*256)/256, 256>>>((const float*)pF2max, scl + 5*CMAX, bia + 5*CMAX, (float*)d_out);
}

// round 5
// speedup vs baseline: 2.2529x; 2.2529x over previous
#include <cuda_runtime.h>
#include <cuda_bf16.h>
#include <cstdint>
#include <cstddef>

#define BB 32
#define N1 2048
#define S1 512
#define S2 256
#define NS 32
#define R2C 0.25f
#define NSLOT 64
#define CMAX 256
#define NT1 (BB*S1*NS)
#define NT2 (BB*S2*NS)
#define POOLE 67108864ull   // = NT1*128 = NT2*256

// ---------------- static device buffers ----------------
__device__ float g_F0[(size_t)BB*64*N1];
__device__ float g_F1t[(size_t)BB*N1*64];       // conv2 out, sample-major [b][n][64]
__device__ float g_nx1[(size_t)BB*S1*3];
__device__ int   g_fps1[BB*S1];
__device__ int   g_gi1[(size_t)BB*S1*NS];
__device__ float g_F1max[(size_t)BB*S1*128];
__device__ float g_nx2[(size_t)BB*S2*3];
__device__ int   g_fps2[BB*S2];
__device__ int   g_gi2[(size_t)BB*S2*NS];
__device__ float g_F2max[(size_t)BB*S2*256];

__device__ __nv_bfloat16 g_Ah[POOLE];
__device__ __nv_bfloat16 g_Al[POOLE];
__device__ __nv_bfloat16 g_Bh[POOLE];
__device__ __nv_bfloat16 g_Bl[POOLE];
__device__ float         g_G [POOLE];
__device__ __nv_bfloat16 g_Wh[163840];
__device__ __nv_bfloat16 g_Wl[163840];

__device__ double g_psum[6*NSLOT*CMAX];
__device__ double g_psq [6*NSLOT*CMAX];
__device__ float  g_scale[6*CMAX];
__device__ float  g_bias [6*CMAX];

// ---------------- mma helper ----------------
__device__ __forceinline__ void mma16816(float* c, const uint32_t* a, uint32_t b0, uint32_t b1) {
    asm volatile("mma.sync.aligned.m16n8k16.row.col.f32.bf16.bf16.f32 "
        "{%0,%1,%2,%3}, {%4,%5,%6,%7}, {%8,%9}, {%0,%1,%2,%3};"
        : "+f"(c[0]), "+f"(c[1]), "+f"(c[2]), "+f"(c[3])
        : "r"(a[0]), "r"(a[1]), "r"(a[2]), "r"(a[3]), "r"(b0), "r"(b1));
}

// ---------------- BN finalize ----------------
__global__ void k_fin(const double* __restrict__ psum, const double* __restrict__ psq,
                      float* __restrict__ sc, float* __restrict__ bi, int C, double invM)
{
    int t = threadIdx.x;
    if (t >= C) return;
    double s = 0.0, q = 0.0;
    for (int k = 0; k < NSLOT; k++) { s += psum[k*CMAX + t]; q += psq[k*CMAX + t]; }
    double mean = s * invM;
    double var  = q * invM - mean * mean;
    if (var < 0.0) var = 0.0;
    double sv = 1.0 / sqrt(var + 1e-5);
    sc[t] = (float)sv;
    bi[t] = (float)(-mean * sv);
}

// ---------------- weight split fp32 -> bf16 hi/lo ----------------
__global__ void k_wsplit(const float* __restrict__ src, __nv_bfloat16* __restrict__ dh,
                         __nv_bfloat16* __restrict__ dl, int n)
{
    int i = blockIdx.x*256 + threadIdx.x;
    if (i >= n) return;
    float v = src[i];
    __nv_bfloat16 h = __float2bfloat16(v);
    dh[i] = h;
    dl[i] = __float2bfloat16(v - __bfloat162float(h));
}

// ---------------- conv1 ----------------
__global__ void k_conv1(const float* __restrict__ x, const float* __restrict__ W,
                        float* __restrict__ F0, double* __restrict__ psum, double* __restrict__ psq)
{
    int c = blockIdx.x, b = blockIdx.y, t = threadIdx.x;
    float w0 = W[c*3], w1 = W[c*3+1], w2 = W[c*3+2];
    const float* xb = x + (size_t)b*3*N1;
    float* o = F0 + ((size_t)b*64 + c)*N1;
    float ls = 0.f, lq = 0.f;
    for (int n = t; n < N1; n += 256) {
        float v = w0*xb[n] + w1*xb[N1+n] + w2*xb[2*N1+n];
        o[n] = v; ls += v; lq += v*v;
    }
    for (int off = 16; off; off >>= 1) {
        ls += __shfl_down_sync(0xffffffffu, ls, off);
        lq += __shfl_down_sync(0xffffffffu, lq, off);
    }
    __shared__ float ws_[8], wq_[8];
    if ((t & 31) == 0) { ws_[t >> 5] = ls; wq_[t >> 5] = lq; }
    __syncthreads();
    if (t == 0) {
        float S = 0.f, Q = 0.f;
        for (int i = 0; i < 8; i++) { S += ws_[i]; Q += wq_[i]; }
        atomicAdd(&psum[(b & (NSLOT-1))*CMAX + c], (double)S);
        atomicAdd(&psq [(b & (NSLOT-1))*CMAX + c], (double)Q);
    }
}

// ---------------- conv2: writes F1t sample-major [b][n][64] ----------------
__global__ void k_conv2(const float* __restrict__ F0, const float* __restrict__ W,
                        const float* __restrict__ sc0, const float* __restrict__ bi0,
                        float* __restrict__ F1t, double* __restrict__ psum, double* __restrict__ psq)
{
    __shared__ float in_t[64*64];
    __shared__ float ws[64*65];
    __shared__ float pspart[4*64], pqpart[4*64];
    int tile = blockIdx.x, b = blockIdx.y, t = threadIdx.x;
    for (int i = t; i < 4096; i += 256) { int c = i >> 6, k = i & 63; ws[c*65 + k] = W[i]; }
    const float* F0b = F0 + (size_t)b*64*N1 + tile*64;
    for (int i = t; i < 4096; i += 256) {
        int k = i >> 6, nn = i & 63;
        float v = F0b[(size_t)k*N1 + nn]*sc0[k] + bi0[k];
        in_t[k*64 + nn] = fmaxf(v, 0.f);
    }
    __syncthreads();
    int c = t & 63, nq = t >> 6;
    float acc[16];
    #pragma unroll
    for (int j = 0; j < 16; j++) acc[j] = 0.f;
    for (int k = 0; k < 64; k++) {
        float wv = ws[c*65 + k];
        const float* ar = &in_t[k*64 + nq*16];
        #pragma unroll
        for (int jq = 0; jq < 4; jq++) {
            float4 a = *(const float4*)(ar + 4*jq);
            acc[4*jq+0] += wv*a.x; acc[4*jq+1] += wv*a.y;
            acc[4*jq+2] += wv*a.z; acc[4*jq+3] += wv*a.w;
        }
    }
    float lsum = 0.f, lsq = 0.f;
    #pragma unroll
    for (int j = 0; j < 16; j++) { float v = acc[j]; lsum += v; lsq += v*v; }
    pspart[nq*64 + c] = lsum; pqpart[nq*64 + c] = lsq;
    __syncthreads();   // done reading ws as weights
    #pragma unroll
    for (int j = 0; j < 16; j++) ws[(nq*16 + j)*65 + c] = acc[j];
    if (t < 64) {
        float s = pspart[t] + pspart[64+t] + pspart[128+t] + pspart[192+t];
        float q = pqpart[t] + pqpart[64+t] + pqpart[128+t] + pqpart[192+t];
        int slot = (blockIdx.x + 32*blockIdx.y) & (NSLOT-1);
        atomicAdd(&psum[slot*CMAX + t], (double)s);
        atomicAdd(&psq [slot*CMAX + t], (double)q);
    }
    __syncthreads();
    size_t nbase = (size_t)b*N1 + tile*64;
    for (int i = t; i < 4096; i += 256) {
        int n = i >> 6, cc = i & 63;
        F1t[(nbase + n)*64 + cc] = ws[n*65 + cc];
    }
}

// ---------------- FPS (smem-resident, exact fp match with reference) ----------------
template<int N, int S>
__global__ void __launch_bounds__(256) k_fps(const float* __restrict__ P, size_t bstride,
                      size_t pstride, size_t cstride,
                      int* __restrict__ outIdx, float* __restrict__ outXYZ)
{
    int b = blockIdx.x, t = threadIdx.x, wid = t >> 5, lane = t & 31;
    const float* Pb = P + (size_t)b*bstride;
    __shared__ float xs[N], ys[N], zs[N], dist[N];
    __shared__ float wv[8]; __shared__ int wi[8]; __shared__ int sfar;
    for (int j = t; j < N; j += 256) {
        xs[j] = Pb[(size_t)j*pstride];
        ys[j] = Pb[(size_t)j*pstride + cstride];
        zs[j] = Pb[(size_t)j*pstride + 2*cstride];
        dist[j] = 1e10f;
    }
    if (t == 0) sfar = 0;
    __syncthreads();
    for (int s = 0; s < S; s++) {
        int far = sfar;
        float fx = xs[far], fy = ys[far], fz = zs[far];
        if (t == 0) {
            outIdx[(size_t)b*S + s] = far;
            float* o = &outXYZ[((size_t)b*S + s)*3];
            o[0] = fx; o[1] = fy; o[2] = fz;
        }
        float bv = -1.f; int bi = 0x7fffffff;
        for (int j = t; j < N; j += 256) {
            float dx = __fsub_rn(xs[j], fx);
            float dy = __fsub_rn(ys[j], fy);
            float dz = __fsub_rn(zs[j], fz);
            float d = __fadd_rn(__fadd_rn(__fmul_rn(dx,dx), __fmul_rn(dy,dy)), __fmul_rn(dz,dz));
            float nd = fminf(dist[j], d);
            dist[j] = nd;
            if (nd > bv) { bv = nd; bi = j; }
        }
        #pragma unroll
        for (int off = 16; off; off >>= 1) {
            float ov = __shfl_down_sync(0xffffffffu, bv, off);
            int   oi = __shfl_down_sync(0xffffffffu, bi, off);
            if (ov > bv || (ov == bv && oi < bi)) { bv = ov; bi = oi; }
        }
        if (lane == 0) { wv[wid] = bv; wi[wid] = bi; }
        __syncthreads();
        if (t == 0) {
            float best = wv[0]; int besti = wi[0];
            #pragma unroll
            for (int k = 1; k < 8; k++)
                if (wv[k] > best || (wv[k] == best && wi[k] < besti)) { best = wv[k]; besti = wi[k]; }
            sfar = besti;
        }
        __syncthreads();
    }
}

// ---------------- ball query ----------------
__global__ void k_ball(const float* __restrict__ C, size_t bstrideC, size_t pstride, size_t cstride,
                       int N, const float* __restrict__ Q, int S, int* __restrict__ gi)
{
    int wid = threadIdx.x >> 5, lane = threadIdx.x & 31;
    int g = blockIdx.x*4 + wid;
    int b = g / S;
    const float* Cb = C + (size_t)b*bstrideC;
    const float* q = Q + (size_t)g*3;
    float qx = q[0], qy = q[1], qz = q[2];
    __shared__ int buf[4][NS];
    int cnt = 0;
    for (int base = 0; base < N && cnt < NS; base += 32) {
        int j = base + lane;
        float dx = __fsub_rn(Cb[(size_t)j*pstride], qx);
        float dy = __fsub_rn(Cb[(size_t)j*pstride + cstride], qy);
        float dz = __fsub_rn(Cb[(size_t)j*pstride + 2*cstride], qz);
        float d = __fadd_rn(__fadd_rn(__fmul_rn(dx,dx), __fmul_rn(dy,dy)), __fmul_rn(dz,dz));
        bool ok = !(d > R2C);
        unsigned m = __ballot_sync(0xffffffffu, ok);
        int pos = cnt + __popc(m & ((1u << lane) - 1u));
        if (ok && pos < NS) buf[wid][pos] = j;
        cnt += __popc(m);
    }
    __syncwarp();
    int first = buf[wid][0];
    int mm = cnt < NS ? cnt : NS;
    int v = (lane < mm) ? buf[wid][lane] : first;
    gi[(size_t)g*NS + lane] = v;
}

// ---------------- gather: build A (bf16 hi/lo), [col][CIN] K-major ----------------
template<int CH>
__global__ void __launch_bounds__(256) k_gatherA(
    const float* __restrict__ src, int NP,
    const float* __restrict__ sc, const float* __restrict__ bi,
    const int* __restrict__ gi, const int* __restrict__ fpsidx, int S,
    __nv_bfloat16* __restrict__ Ah, __nv_bfloat16* __restrict__ Al)
{
    constexpr int CIN = 2*CH;
    __shared__ float fc[CH]; __shared__ int gix[32];
    int g = blockIdx.x, t = threadIdx.x, wid = t >> 5, lane = t & 31;
    int b = g / S, s = g % S;
    if (t < 32) gix[t] = gi[(size_t)g*NS + t];
    if (t < CH) {
        int ci = fpsidx[(size_t)b*S + s];
        float v = src[((size_t)b*NP + ci)*CH + t]*sc[t] + bi[t];
        fc[t] = fmaxf(v, 0.f);
    }
    __syncthreads();
    for (int k = wid; k < NS; k += 8) {
        size_t row = (size_t)b*NP + gix[k];
        size_t ob = ((size_t)g*NS + k)*CIN;
        for (int c = lane; c < CH; c += 32) {
            float v = src[row*CH + c]*sc[c] + bi[c];
            v = fmaxf(v, 0.f);
            float d = v - fc[c];
            __nv_bfloat16 h = __float2bfloat16(d);
            Ah[ob + c] = h;
            Al[ob + c] = __float2bfloat16(d - __bfloat162float(h));
            float f = fc[c];
            __nv_bfloat16 fh = __float2bfloat16(f);
            Ah[ob + CH + c] = fh;
            Al[ob + CH + c] = __float2bfloat16(f - __bfloat162float(fh));
        }
    }
}

// ---------------- convert G (fp32) -> B (bf16 hi/lo) with bn+relu ----------------
template<int C>
__global__ void k_mkB(const float* __restrict__ G, const float* __restrict__ sc,
                      const float* __restrict__ bi,
                      __nv_bfloat16* __restrict__ Bh, __nv_bfloat16* __restrict__ Bl)
{
    size_t i4 = ((size_t)blockIdx.x*256 + threadIdx.x)*4;
    float4 gg = *(const float4*)&G[i4];
    int m = (int)(i4 & (C-1));
    float v[4] = {gg.x, gg.y, gg.z, gg.w};
    __nv_bfloat16 hh[4], ll[4];
    #pragma unroll
    for (int j = 0; j < 4; j++) {
        float w = fmaxf(v[j]*sc[m+j] + bi[m+j], 0.f);
        hh[j] = __float2bfloat16(w);
        ll[j] = __float2bfloat16(w - __bfloat162float(hh[j]));
    }
    *(uint2*)&Bh[i4] = *(uint2*)hh;
    *(uint2*)&Bl[i4] = *(uint2*)ll;
}

// ---------------- mma.sync GEMM: C[128,128] tile = W[128,K] x Acols[128,K]^T ----------------
// 3-pass bf16 split: Wh*Ah + Wh*Al + Wl*Ah
template<int K, int COUT, bool WRITE_G>
__global__ void __launch_bounds__(256) k_mma(
    const __nv_bfloat16* __restrict__ Wh, const __nv_bfloat16* __restrict__ Wl,
    const __nv_bfloat16* __restrict__ Ah, const __nv_bfloat16* __restrict__ Al,
    float* __restrict__ G, float* __restrict__ Fmax,
    double* __restrict__ psum, double* __restrict__ psq)
{
    __shared__ __align__(16) __nv_bfloat16 Wt[128*40];
    __shared__ __align__(16) __nv_bfloat16 At[128*40];
    __shared__ float sred[128], qred[128];
    int t = threadIdx.x, wid = t >> 5, lane = t & 31;
    int r4 = lane >> 2, q = lane & 3;
    int ntile = blockIdx.x, mtile = blockIdx.y;
    size_t colbase = (size_t)ntile*128;
    int mbase = mtile*128;
    int m0w = (wid & 3)*32, n0w = (wid >> 2)*64;

    for (int i = t; i < 128; i += 256) { sred[i] = 0.f; qred[i] = 0.f; }

    constexpr int CPP = K/32;       // k-chunks per pass
    constexpr int NCH = 3*CPP;

    float acc[2][8][4];
    #pragma unroll
    for (int im = 0; im < 2; im++)
        #pragma unroll
        for (int in_ = 0; in_ < 8; in_++)
            #pragma unroll
            for (int c = 0; c < 4; c++) acc[im][in_][c] = 0.f;

    int row0 = t >> 2, seg0 = t & 3;
    int row1 = (t + 256) >> 2, seg1 = (t + 256) & 3;

    uint4 pw0, pw1, pa0, pa1;
    {   // prefetch chunk 0 (pass 0: Wh, Ah; kc 0)
        const __nv_bfloat16* Wp = Wh + (size_t)mbase*K;
        const __nv_bfloat16* Ap = Ah + colbase*K;
        pw0 = *(const uint4*)(Wp + (size_t)row0*K + seg0*8);
        pa0 = *(const uint4*)(Ap + (size_t)row0*K + seg0*8);
        pw1 = *(const uint4*)(Wp + (size_t)row1*K + seg1*8);
        pa1 = *(const uint4*)(Ap + (size_t)row1*K + seg1*8);
    }

    const uint32_t* Wu = (const uint32_t*)Wt;
    const uint32_t* Au = (const uint32_t*)At;

    #pragma unroll 1
    for (int ch = 0; ch < NCH; ch++) {
        __syncthreads();
        *(uint4*)&Wt[row0*40 + seg0*8] = pw0;
        *(uint4*)&At[row0*40 + seg0*8] = pa0;
        *(uint4*)&Wt[row1*40 + seg1*8] = pw1;
        *(uint4*)&At[row1*40 + seg1*8] = pa1;
        __syncthreads();
        if (ch + 1 < NCH) {
            int c1 = ch + 1;
            int pass = (c1 >= 2*CPP) ? 2 : ((c1 >= CPP) ? 1 : 0);
            int kc = c1 - pass*CPP;
            const __nv_bfloat16* Wp = ((pass == 2) ? Wl : Wh) + (size_t)mbase*K + kc*32;
            const __nv_bfloat16* Ap = ((pass == 1) ? Al : Ah) + colbase*K + kc*32;
            pw0 = *(const uint4*)(Wp + (size_t)row0*K + seg0*8);
            pa0 = *(const uint4*)(Ap + (size_t)row0*K + seg0*8);
            pw1 = *(const uint4*)(Wp + (size_t)row1*K + seg1*8);
            pa1 = *(const uint4*)(Ap + (size_t)row1*K + seg1*8);
        }
        #pragma unroll
        for (int kk = 0; kk < 2; kk++) {
            int ko = kk*8 + q;
            uint32_t a[2][4];
            #pragma unroll
            for (int im = 0; im < 2; im++) {
                int base = (m0w + im*16 + r4)*20 + ko;
                a[im][0] = Wu[base];
                a[im][1] = Wu[base + 8*20];
                a[im][2] = Wu[base + 4];
                a[im][3] = Wu[base + 8*20 + 4];
            }
            #pragma unroll
            for (int in_ = 0; in_ < 8; in_++) {
                int nb = (n0w + in_*8 + r4)*20 + ko;
                uint32_t b0 = Au[nb];
                uint32_t b1 = Au[nb + 4];
                mma16816(acc[0][in_], a[0], b0, b1);
                mma16816(acc[1][in_], a[1], b0, b1);
            }
        }
    }

    // ---------------- epilogue ----------------
    if (WRITE_G) {
        #pragma unroll
        for (int im = 0; im < 2; im++)
            #pragma unroll
            for (int in_ = 0; in_ < 8; in_++) {
                size_t col = colbase + n0w + in_*8 + q*2;
                int mA = mbase + m0w + im*16 + r4;
                G[col*COUT + mA]       = acc[im][in_][0];
                G[(col+1)*COUT + mA]   = acc[im][in_][1];
                G[col*COUT + mA + 8]   = acc[im][in_][2];
                G[(col+1)*COUT + mA+8] = acc[im][in_][3];
            }
    }
    #pragma unroll
    for (int im = 0; im < 2; im++) {
        float sA = 0.f, sB = 0.f, qA = 0.f, qB = 0.f;
        float mxA[2] = {-3.4e38f, -3.4e38f}, mxB[2] = {-3.4e38f, -3.4e38f};
        #pragma unroll
        for (int in_ = 0; in_ < 8; in_++) {
            int gh = in_ >> 2;
            float v0 = acc[im][in_][0], v1 = acc[im][in_][1];
            float v2 = acc[im][in_][2], v3 = acc[im][in_][3];
            sA += v0 + v1; qA += v0*v0 + v1*v1;
            sB += v2 + v3; qB += v2*v2 + v3*v3;
            mxA[gh] = fmaxf(mxA[gh], fmaxf(v0, v1));
            mxB[gh] = fmaxf(mxB[gh], fmaxf(v2, v3));
        }
        #pragma unroll
        for (int off = 1; off <= 2; off <<= 1) {
            sA += __shfl_xor_sync(0xffffffffu, sA, off);
            qA += __shfl_xor_sync(0xffffffffu, qA, off);
            sB += __shfl_xor_sync(0xffffffffu, sB, off);
            qB += __shfl_xor_sync(0xffffffffu, qB, off);
            #pragma unroll
            for (int gh = 0; gh < 2; gh++) {
                mxA[gh] = fmaxf(mxA[gh], __shfl_xor_sync(0xffffffffu, mxA[gh], off));
                mxB[gh] = fmaxf(mxB[gh], __shfl_xor_sync(0xffffffffu, mxB[gh], off));
            }
        }
        if (q == 0) {
            int lmA = m0w + im*16 + r4, lmB = lmA + 8;
            if (!WRITE_G) {
                size_t g0 = (size_t)ntile*4 + (n0w >> 5);
                Fmax[g0*COUT + mbase + lmA]     = mxA[0];
                Fmax[(g0+1)*COUT + mbase + lmA] = mxA[1];
                Fmax[g0*COUT + mbase + lmB]     = mxB[0];
                Fmax[(g0+1)*COUT + mbase + lmB] = mxB[1];
            }
            atomicAdd(&sred[lmA], sA); atomicAdd(&qred[lmA], qA);
            atomicAdd(&sred[lmB], sB); atomicAdd(&qred[lmB], qB);
        }
    }
    __syncthreads();
    if (t < 128) {
        int slot = (ntile + mtile) & (NSLOT-1);
        atomicAdd(&psum[slot*CMAX + mbase + t], (double)sred[t]);
        atomicAdd(&psq [slot*CMAX + mbase + t], (double)qred[t]);
    }
}

// ---------------- final output f2 ----------------
__global__ void k_out_f2(const float* __restrict__ Fmax, const float* __restrict__ sc,
                         const float* __restrict__ bi, float* __restrict__ out)
{
    size_t i = (size_t)blockIdx.x*256 + threadIdx.x;
    int s = (int)(i & 255);
    size_t r = i >> 8;
    int c = (int)(r & 255);
    int b = (int)(r >> 8);
    float v = Fmax[((size_t)(b*256 + s))*256 + c]*sc[c] + bi[c];
    out[24576 + i] = fmaxf(v, 0.f);
}

// ---------------- launch ----------------
extern "C" void kernel_launch(void* const* d_in, const int* in_sizes, int n_in,
                              void* d_out, int out_size)
{
    const float* x  = (const float*)d_in[0];
    const float* w1 = (const float*)d_in[1];
    const float* w2 = (const float*)d_in[2];
    const float* wa = (const float*)d_in[3];
    const float* wb = (const float*)d_in[4];
    const float* wc = (const float*)d_in[5];
    const float* wd = (const float*)d_in[6];

    void *pF0, *pF1t, *pnx1, *pfps1, *pgi1, *pF1max, *pnx2, *pfps2, *pgi2, *pF2max;
    void *pAh, *pAl, *pBh, *pBl, *pG, *pWh, *pWl, *ppsum, *ppsq, *pscale, *pbias;
    cudaGetSymbolAddress(&pF0, g_F0);       cudaGetSymbolAddress(&pF1t, g_F1t);
    cudaGetSymbolAddress(&pnx1, g_nx1);     cudaGetSymbolAddress(&pfps1, g_fps1);
    cudaGetSymbolAddress(&pgi1, g_gi1);     cudaGetSymbolAddress(&pF1max, g_F1max);
    cudaGetSymbolAddress(&pnx2, g_nx2);     cudaGetSymbolAddress(&pfps2, g_fps2);
    cudaGetSymbolAddress(&pgi2, g_gi2);     cudaGetSymbolAddress(&pF2max, g_F2max);
    cudaGetSymbolAddress(&pAh, g_Ah);       cudaGetSymbolAddress(&pAl, g_Al);
    cudaGetSymbolAddress(&pBh, g_Bh);       cudaGetSymbolAddress(&pBl, g_Bl);
    cudaGetSymbolAddress(&pG, g_G);         cudaGetSymbolAddress(&pWh, g_Wh);
    cudaGetSymbolAddress(&pWl, g_Wl);
    cudaGetSymbolAddress(&ppsum, g_psum);   cudaGetSymbolAddress(&ppsq, g_psq);
    cudaGetSymbolAddress(&pscale, g_scale); cudaGetSymbolAddress(&pbias, g_bias);

    double* psum = (double*)ppsum;
    double* psq  = (double*)ppsq;
    float* scl = (float*)pscale;
    float* bia = (float*)pbias;
    __nv_bfloat16* Wh = (__nv_bfloat16*)pWh;
    __nv_bfloat16* Wl = (__nv_bfloat16*)pWl;
    __nv_bfloat16* Ah = (__nv_bfloat16*)pAh;
    __nv_bfloat16* Al = (__nv_bfloat16*)pAl;
    __nv_bfloat16* Bh = (__nv_bfloat16*)pBh;
    __nv_bfloat16* Bl = (__nv_bfloat16*)pBl;
    float* G = (float*)pG;

    cudaMemsetAsync(psum, 0, 6*NSLOT*CMAX*sizeof(double), 0);
    cudaMemsetAsync(psq,  0, 6*NSLOT*CMAX*sizeof(double), 0);

    // weight splits
    k_wsplit<<<64,256>>>(wa, Wh + 0,      Wl + 0,      16384);
    k_wsplit<<<64,256>>>(wb, Wh + 16384,  Wl + 16384,  16384);
    k_wsplit<<<256,256>>>(wc, Wh + 32768, Wl + 32768,  65536);
    k_wsplit<<<256,256>>>(wd, Wh + 98304, Wl + 98304,  65536);

    // convs + BN
    k_conv1<<<dim3(64,BB), 256>>>(x, w1, (float*)pF0, psum, psq);
    k_fin<<<1,64>>>(psum, psq, scl, bia, 64, 1.0/((double)BB*N1));
    k_conv2<<<dim3(32,BB), 256>>>((const float*)pF0, w2, scl, bia,
                                  (float*)pF1t, psum + NSLOT*CMAX, psq + NSLOT*CMAX);
    k_fin<<<1,64>>>(psum + NSLOT*CMAX, psq + NSLOT*CMAX, scl + CMAX, bia + CMAX, 64, 1.0/((double)BB*N1));

    // FPS + ball stage 1 (raw coords, x is [B,3,N] channel-major)
    k_fps<N1,S1><<<BB,256>>>(x, (size_t)3*N1, 1, N1, (int*)pfps1, (float*)pnx1);
    k_ball<<<BB*S1/4,128>>>(x, (size_t)3*N1, 1, N1, N1, (const float*)pnx1, S1, (int*)pgi1);

    // sg1
    k_gatherA<64><<<BB*S1, 256>>>((const float*)pF1t, N1, scl + CMAX, bia + CMAX,
                                  (const int*)pgi1, (const int*)pfps1, S1, Ah, Al);
    k_mma<128,128,true><<<dim3(NT1/128,1), 256>>>(Wh + 0, Wl + 0, Ah, Al,
        G, nullptr, psum + 2*NSLOT*CMAX, psq + 2*NSLOT*CMAX);
    k_fin<<<1,128>>>(psum + 2*NSLOT*CMAX, psq + 2*NSLOT*CMAX, scl + 2*CMAX, bia + 2*CMAX, 128, 1.0/((double)NT1));
    k_mkB<128><<<POOLE/1024, 256>>>(G, scl + 2*CMAX, bia + 2*CMAX, Bh, Bl);
    k_mma<128,128,false><<<dim3(NT1/128,1), 256>>>(Wh + 16384, Wl + 16384, Bh, Bl,
        nullptr, (float*)pF1max, psum + 3*NSLOT*CMAX, psq + 3*NSLOT*CMAX);
    k_fin<<<1,128>>>(psum + 3*NSLOT*CMAX, psq + 3*NSLOT*CMAX, scl + 3*CMAX, bia + 3*CMAX, 128, 1.0/((double)NT1));

    // FPS + ball stage 2 (nx1 is [B,S1,3] point-major)
    k_fps<S1,S2><<<BB,256>>>((const float*)pnx1, (size_t)S1*3, 3, 1, (int*)pfps2, (float*)pnx2);
    k_ball<<<BB*S2/4,128>>>((const float*)pnx1, (size_t)S1*3, 3, 1, S1, (const float*)pnx2, S2, (int*)pgi2);

    // sg2
    k_gatherA<128><<<BB*S2, 256>>>((const float*)pF1max, S1, scl + 3*CMAX, bia + 3*CMAX,
                                   (const int*)pgi2, (const int*)pfps2, S2, Ah, Al);
    k_mma<256,256,true><<<dim3(NT2/128,2), 256>>>(Wh + 32768, Wl + 32768, Ah, Al,
        G, nullptr, psum + 4*NSLOT*CMAX, psq + 4*NSLOT*CMAX);
    k_fin<<<1,256>>>(psum + 4*NSLOT*CMAX, psq + 4*NSLOT*CMAX, scl + 4*CMAX, bia + 4*CMAX, 256, 1.0/((double)NT2));
    k_mkB<256><<<POOLE/1024, 256>>>(G, scl + 4*CMAX, bia + 4*CMAX, Bh, Bl);
    k_mma<256,256,false><<<dim3(NT2/128,2), 256>>>(Wh + 98304, Wl + 98304, Bh, Bl,
        nullptr, (float*)pF2max, psum + 5*NSLOT*CMAX, psq + 5*NSLOT*CMAX);
    k_fin<<<1,256>>>(psum + 5*NSLOT*CMAX, psq + 5*NSLOT*CMAX, scl + 5*CMAX, bia + 5*CMAX, 256, 1.0/((double)NT2));

    // outputs
    cudaMemcpyAsync(d_out, pnx2, (size_t)BB*S2*3*sizeof(float), cudaMemcpyDeviceToDevice, 0);
    k_out_f2<<<(BB*256*256)/256, 256>>>((const float*)pF2max, scl + 5*CMAX, bia + 5*CMAX, (float*)d_out);
}

// round 7
// speedup vs baseline: 2.4862x; 1.1036x over previous
#include <cuda_runtime.h>
#include <cuda_bf16.h>
#include <cstdint>
#include <cstddef>

#define BB 32
#define N1 2048
#define S1 512
#define S2 256
#define NS 32
#define R2C 0.25f
#define NSLOT 64
#define CMAX 256
#define NT1 (BB*S1*NS)
#define NT2 (BB*S2*NS)
#define POOLE 67108864ull   // = NT1*128 = NT2*256

// ---------------- static device buffers ----------------
__device__ float g_F0[(size_t)BB*64*N1];
__device__ float g_F1t[(size_t)BB*N1*64];       // conv2 out, sample-major [b][n][64]
__device__ float g_nx1[(size_t)BB*S1*3];
__device__ int   g_fps1[BB*S1];
__device__ int   g_gi1[(size_t)BB*S1*NS];
__device__ float g_F1max[(size_t)BB*S1*128];
__device__ float g_nx2[(size_t)BB*S2*3];
__device__ int   g_fps2[BB*S2];
__device__ int   g_gi2[(size_t)BB*S2*NS];
__device__ float g_F2max[(size_t)BB*S2*256];

__device__ float g_A[POOLE];                    // fp32 gathered operand
__device__ float g_G[POOLE];                    // fp32 first-layer output per stage

__device__ double g_psum[6*NSLOT*CMAX];
__device__ double g_psq [6*NSLOT*CMAX];
__device__ float  g_scale[6*CMAX];
__device__ float  g_bias [6*CMAX];

// ---------------- helpers ----------------
__device__ __forceinline__ void mma16816(float* c, const uint32_t* a, uint32_t b0, uint32_t b1) {
    asm volatile("mma.sync.aligned.m16n8k16.row.col.f32.bf16.bf16.f32 "
        "{%0,%1,%2,%3}, {%4,%5,%6,%7}, {%8,%9}, {%0,%1,%2,%3};"
        : "+f"(c[0]), "+f"(c[1]), "+f"(c[2]), "+f"(c[3])
        : "r"(a[0]), "r"(a[1]), "r"(a[2]), "r"(a[3]), "r"(b0), "r"(b1));
}

__device__ __forceinline__ void split4(float v0, float v1, float v2, float v3,
                                       uint2& hi, uint2& lo)
{
    __nv_bfloat162 h0 = __floats2bfloat162_rn(v0, v1);
    __nv_bfloat162 h1 = __floats2bfloat162_rn(v2, v3);
    float2 f0 = __bfloat1622float2(h0);
    float2 f1 = __bfloat1622float2(h1);
    __nv_bfloat162 l0 = __floats2bfloat162_rn(v0 - f0.x, v1 - f0.y);
    __nv_bfloat162 l1 = __floats2bfloat162_rn(v2 - f1.x, v3 - f1.y);
    hi.x = *reinterpret_cast<uint32_t*>(&h0);
    hi.y = *reinterpret_cast<uint32_t*>(&h1);
    lo.x = *reinterpret_cast<uint32_t*>(&l0);
    lo.y = *reinterpret_cast<uint32_t*>(&l1);
}

// ---------------- BN finalize ----------------
__global__ void k_fin(const double* __restrict__ psum, const double* __restrict__ psq,
                      float* __restrict__ sc, float* __restrict__ bi, int C, double invM)
{
    int t = threadIdx.x;
    if (t >= C) return;
    double s = 0.0, q = 0.0;
    for (int k = 0; k < NSLOT; k++) { s += psum[k*CMAX + t]; q += psq[k*CMAX + t]; }
    double mean = s * invM;
    double var  = q * invM - mean * mean;
    if (var < 0.0) var = 0.0;
    double sv = 1.0 / sqrt(var + 1e-5);
    sc[t] = (float)sv;
    bi[t] = (float)(-mean * sv);
}

// ---------------- conv1 ----------------
__global__ void k_conv1(const float* __restrict__ x, const float* __restrict__ W,
                        float* __restrict__ F0, double* __restrict__ psum, double* __restrict__ psq)
{
    int c = blockIdx.x, b = blockIdx.y, t = threadIdx.x;
    float w0 = W[c*3], w1 = W[c*3+1], w2 = W[c*3+2];
    const float* xb = x + (size_t)b*3*N1;
    float* o = F0 + ((size_t)b*64 + c)*N1;
    float ls = 0.f, lq = 0.f;
    for (int n = t; n < N1; n += 256) {
        float v = w0*xb[n] + w1*xb[N1+n] + w2*xb[2*N1+n];
        o[n] = v; ls += v; lq += v*v;
    }
    for (int off = 16; off; off >>= 1) {
        ls += __shfl_down_sync(0xffffffffu, ls, off);
        lq += __shfl_down_sync(0xffffffffu, lq, off);
    }
    __shared__ float ws_[8], wq_[8];
    if ((t & 31) == 0) { ws_[t >> 5] = ls; wq_[t >> 5] = lq; }
    __syncthreads();
    if (t == 0) {
        float S = 0.f, Q = 0.f;
        for (int i = 0; i < 8; i++) { S += ws_[i]; Q += wq_[i]; }
        atomicAdd(&psum[(b & (NSLOT-1))*CMAX + c], (double)S);
        atomicAdd(&psq [(b & (NSLOT-1))*CMAX + c], (double)Q);
    }
}

// ---------------- conv2: writes F1t sample-major [b][n][64] ----------------
__global__ void k_conv2(const float* __restrict__ F0, const float* __restrict__ W,
                        const float* __restrict__ sc0, const float* __restrict__ bi0,
                        float* __restrict__ F1t, double* __restrict__ psum, double* __restrict__ psq)
{
    __shared__ float in_t[64*64];
    __shared__ float ws[64*65];
    __shared__ float pspart[4*64], pqpart[4*64];
    int tile = blockIdx.x, b = blockIdx.y, t = threadIdx.x;
    for (int i = t; i < 4096; i += 256) { int c = i >> 6, k = i & 63; ws[c*65 + k] = W[i]; }
    const float* F0b = F0 + (size_t)b*64*N1 + tile*64;
    for (int i = t; i < 4096; i += 256) {
        int k = i >> 6, nn = i & 63;
        float v = F0b[(size_t)k*N1 + nn]*sc0[k] + bi0[k];
        in_t[k*64 + nn] = fmaxf(v, 0.f);
    }
    __syncthreads();
    int c = t & 63, nq = t >> 6;
    float acc[16];
    #pragma unroll
    for (int j = 0; j < 16; j++) acc[j] = 0.f;
    for (int k = 0; k < 64; k++) {
        float wv = ws[c*65 + k];
        const float* ar = &in_t[k*64 + nq*16];
        #pragma unroll
        for (int jq = 0; jq < 4; jq++) {
            float4 a = *(const float4*)(ar + 4*jq);
            acc[4*jq+0] += wv*a.x; acc[4*jq+1] += wv*a.y;
            acc[4*jq+2] += wv*a.z; acc[4*jq+3] += wv*a.w;
        }
    }
    float lsum = 0.f, lsq = 0.f;
    #pragma unroll
    for (int j = 0; j < 16; j++) { float v = acc[j]; lsum += v; lsq += v*v; }
    pspart[nq*64 + c] = lsum; pqpart[nq*64 + c] = lsq;
    __syncthreads();
    #pragma unroll
    for (int j = 0; j < 16; j++) ws[(nq*16 + j)*65 + c] = acc[j];
    if (t < 64) {
        float s = pspart[t] + pspart[64+t] + pspart[128+t] + pspart[192+t];
        float q = pqpart[t] + pqpart[64+t] + pqpart[128+t] + pqpart[192+t];
        int slot = (blockIdx.x + 32*blockIdx.y) & (NSLOT-1);
        atomicAdd(&psum[slot*CMAX + t], (double)s);
        atomicAdd(&psq [slot*CMAX + t], (double)q);
    }
    __syncthreads();
    size_t nbase = (size_t)b*N1 + tile*64;
    for (int i = t; i < 4096; i += 256) {
        int n = i >> 6, cc = i & 63;
        F1t[(nbase + n)*64 + cc] = ws[n*65 + cc];
    }
}

// ---------------- FPS ----------------
template<int N, int S>
__global__ void __launch_bounds__(256) k_fps(const float* __restrict__ P, size_t bstride,
                      size_t pstride, size_t cstride,
                      int* __restrict__ outIdx, float* __restrict__ outXYZ)
{
    int b = blockIdx.x, t = threadIdx.x, wid = t >> 5, lane = t & 31;
    const float* Pb = P + (size_t)b*bstride;
    __shared__ float xs[N], ys[N], zs[N], dist[N];
    __shared__ float wv[8]; __shared__ int wi[8]; __shared__ int sfar;
    for (int j = t; j < N; j += 256) {
        xs[j] = Pb[(size_t)j*pstride];
        ys[j] = Pb[(size_t)j*pstride + cstride];
        zs[j] = Pb[(size_t)j*pstride + 2*cstride];
        dist[j] = 1e10f;
    }
    if (t == 0) sfar = 0;
    __syncthreads();
    for (int s = 0; s < S; s++) {
        int far = sfar;
        float fx = xs[far], fy = ys[far], fz = zs[far];
        if (t == 0) {
            outIdx[(size_t)b*S + s] = far;
            float* o = &outXYZ[((size_t)b*S + s)*3];
            o[0] = fx; o[1] = fy; o[2] = fz;
        }
        float bv = -1.f; int bi = 0x7fffffff;
        for (int j = t; j < N; j += 256) {
            float dx = __fsub_rn(xs[j], fx);
            float dy = __fsub_rn(ys[j], fy);
            float dz = __fsub_rn(zs[j], fz);
            float d = __fadd_rn(__fadd_rn(__fmul_rn(dx,dx), __fmul_rn(dy,dy)), __fmul_rn(dz,dz));
            float nd = fminf(dist[j], d);
            dist[j] = nd;
            if (nd > bv) { bv = nd; bi = j; }
        }
        #pragma unroll
        for (int off = 16; off; off >>= 1) {
            float ov = __shfl_down_sync(0xffffffffu, bv, off);
            int   oi = __shfl_down_sync(0xffffffffu, bi, off);
            if (ov > bv || (ov == bv && oi < bi)) { bv = ov; bi = oi; }
        }
        if (lane == 0) { wv[wid] = bv; wi[wid] = bi; }
        __syncthreads();
        if (t == 0) {
            float best = wv[0]; int besti = wi[0];
            #pragma unroll
            for (int k = 1; k < 8; k++)
                if (wv[k] > best || (wv[k] == best && wi[k] < besti)) { best = wv[k]; besti = wi[k]; }
            sfar = besti;
        }
        __syncthreads();
    }
}

// ---------------- ball query ----------------
__global__ void k_ball(const float* __restrict__ C, size_t bstrideC, size_t pstride, size_t cstride,
                       int N, const float* __restrict__ Q, int S, int* __restrict__ gi)
{
    int wid = threadIdx.x >> 5, lane = threadIdx.x & 31;
    int g = blockIdx.x*4 + wid;
    int b = g / S;
    const float* Cb = C + (size_t)b*bstrideC;
    const float* q = Q + (size_t)g*3;
    float qx = q[0], qy = q[1], qz = q[2];
    __shared__ int buf[4][NS];
    int cnt = 0;
    for (int base = 0; base < N && cnt < NS; base += 32) {
        int j = base + lane;
        float dx = __fsub_rn(Cb[(size_t)j*pstride], qx);
        float dy = __fsub_rn(Cb[(size_t)j*pstride + cstride], qy);
        float dz = __fsub_rn(Cb[(size_t)j*pstride + 2*cstride], qz);
        float d = __fadd_rn(__fadd_rn(__fmul_rn(dx,dx), __fmul_rn(dy,dy)), __fmul_rn(dz,dz));
        bool ok = !(d > R2C);
        unsigned m = __ballot_sync(0xffffffffu, ok);
        int pos = cnt + __popc(m & ((1u << lane) - 1u));
        if (ok && pos < NS) buf[wid][pos] = j;
        cnt += __popc(m);
    }
    __syncwarp();
    int first = buf[wid][0];
    int mm = cnt < NS ? cnt : NS;
    int v = (lane < mm) ? buf[wid][lane] : first;
    gi[(size_t)g*NS + lane] = v;
}

// ---------------- gather: build A fp32, [col][CIN] K-major ----------------
template<int CH>
__global__ void __launch_bounds__(256) k_gatherA(
    const float* __restrict__ src, int NP,
    const float* __restrict__ sc, const float* __restrict__ bi,
    const int* __restrict__ gi, const int* __restrict__ fpsidx, int S,
    float* __restrict__ A)
{
    constexpr int CIN = 2*CH;
    __shared__ float fc[CH]; __shared__ int gix[32];
    int g = blockIdx.x, t = threadIdx.x, wid = t >> 5, lane = t & 31;
    int b = g / S, s = g % S;
    if (t < 32) gix[t] = gi[(size_t)g*NS + t];
    if (t < CH) {
        int ci = fpsidx[(size_t)b*S + s];
        float v = src[((size_t)b*NP + ci)*CH + t]*sc[t] + bi[t];
        fc[t] = fmaxf(v, 0.f);
    }
    __syncthreads();
    for (int k = wid; k < NS; k += 8) {
        size_t row = (size_t)b*NP + gix[k];
        size_t ob = ((size_t)g*NS + k)*CIN;
        for (int c = lane; c < CH; c += 32) {
            float v = src[row*CH + c]*sc[c] + bi[c];
            v = fmaxf(v, 0.f);
            A[ob + c]      = v - fc[c];
            A[ob + CH + c] = fc[c];
        }
    }
}

// ---------------- mma.sync GEMM, in-kernel fp32->bf16 hi/lo split ----------------
// C[128,128] tile = W[128,K](fp32) x A[cols,K](fp32)^T, 3-term split per chunk.
template<int K, int COUT, bool WRITE_G, bool BN>
__global__ void __launch_bounds__(256) k_mma(
    const float* __restrict__ W, const float* __restrict__ A,
    const float* __restrict__ bnsc, const float* __restrict__ bnbi,
    float* __restrict__ G, float* __restrict__ Fmax,
    double* __restrict__ psum, double* __restrict__ psq)
{
    __shared__ __align__(16) __nv_bfloat16 Wht[128*40];
    __shared__ __align__(16) __nv_bfloat16 Wlt[128*40];
    __shared__ __align__(16) __nv_bfloat16 Aht[128*40];
    __shared__ __align__(16) __nv_bfloat16 Alt[128*40];
    __shared__ float sred[128], qred[128];
    __shared__ float scs[256], bis[256];

    int t = threadIdx.x, wid = t >> 5, lane = t & 31;
    int r4 = lane >> 2, q = lane & 3;
    int ntile = blockIdx.x, mtile = blockIdx.y;
    size_t colbase = (size_t)ntile*128;
    int mbase = mtile*128;
    int m0w = (wid & 3)*32, n0w = (wid >> 2)*64;

    for (int i = t; i < 128; i += 256) { sred[i] = 0.f; qred[i] = 0.f; }
    if (BN) for (int i = t; i < K; i += 256) { scs[i] = bnsc[i]; bis[i] = bnbi[i]; }

    float acc[2][8][4];
    #pragma unroll
    for (int im = 0; im < 2; im++)
        #pragma unroll
        for (int in_ = 0; in_ < 8; in_++)
            #pragma unroll
            for (int c = 0; c < 4; c++) acc[im][in_][c] = 0.f;

    constexpr int NCH = K/32;
    const uint32_t* Whu = (const uint32_t*)Wht;
    const uint32_t* Wlu = (const uint32_t*)Wlt;
    const uint32_t* Ahu = (const uint32_t*)Aht;
    const uint32_t* Alu = (const uint32_t*)Alt;

    uint4 pa[4];
    #pragma unroll
    for (int i = 0; i < 4; i++) {
        int idx = t + 256*i, row = idx >> 3, seg = idx & 7;
        pa[i] = *(const uint4*)(A + (colbase + row)*(size_t)K + seg*4);
    }

    #pragma unroll 1
    for (int kc = 0; kc < NCH; kc++) {
        __syncthreads();
        // store A chunk (convert, optional BN+relu)
        #pragma unroll
        for (int i = 0; i < 4; i++) {
            int idx = t + 256*i, row = idx >> 3, seg = idx & 7;
            float4 f = *(float4*)&pa[i];
            if (BN) {
                int kb = kc*32 + seg*4;
                f.x = fmaxf(f.x*scs[kb]   + bis[kb],   0.f);
                f.y = fmaxf(f.y*scs[kb+1] + bis[kb+1], 0.f);
                f.z = fmaxf(f.z*scs[kb+2] + bis[kb+2], 0.f);
                f.w = fmaxf(f.w*scs[kb+3] + bis[kb+3], 0.f);
            }
            uint2 hi, lo;
            split4(f.x, f.y, f.z, f.w, hi, lo);
            *(uint2*)&Aht[row*40 + seg*4] = hi;
            *(uint2*)&Alt[row*40 + seg*4] = lo;
        }
        // load + convert W chunk (L2-resident after first wave)
        #pragma unroll
        for (int i = 0; i < 4; i++) {
            int idx = t + 256*i, row = idx >> 3, seg = idx & 7;
            uint4 wv = *(const uint4*)(W + (size_t)(mbase + row)*K + kc*32 + seg*4);
            float4 f = *(float4*)&wv;
            uint2 hi, lo;
            split4(f.x, f.y, f.z, f.w, hi, lo);
            *(uint2*)&Wht[row*40 + seg*4] = hi;
            *(uint2*)&Wlt[row*40 + seg*4] = lo;
        }
        __syncthreads();
        if (kc + 1 < NCH) {
            #pragma unroll
            for (int i = 0; i < 4; i++) {
                int idx = t + 256*i, row = idx >> 3, seg = idx & 7;
                pa[i] = *(const uint4*)(A + (colbase + row)*(size_t)K + (kc+1)*32 + seg*4);
            }
        }
        #pragma unroll
        for (int kk = 0; kk < 2; kk++) {
            int ko = kk*8 + q;
            uint32_t ah[2][4], al[2][4];
            #pragma unroll
            for (int im = 0; im < 2; im++) {
                int base = (m0w + im*16 + r4)*20 + ko;
                ah[im][0] = Whu[base];       ah[im][1] = Whu[base + 160];
                ah[im][2] = Whu[base + 4];   ah[im][3] = Whu[base + 164];
                al[im][0] = Wlu[base];       al[im][1] = Wlu[base + 160];
                al[im][2] = Wlu[base + 4];   al[im][3] = Wlu[base + 164];
            }
            #pragma unroll
            for (int in_ = 0; in_ < 8; in_++) {
                int nb = (n0w + in_*8 + r4)*20 + ko;
                uint32_t bh0 = Ahu[nb], bh1 = Ahu[nb + 4];
                uint32_t bl0 = Alu[nb], bl1 = Alu[nb + 4];
                mma16816(acc[0][in_], ah[0], bh0, bh1);
                mma16816(acc[1][in_], ah[1], bh0, bh1);
                mma16816(acc[0][in_], ah[0], bl0, bl1);
                mma16816(acc[1][in_], ah[1], bl0, bl1);
                mma16816(acc[0][in_], al[0], bh0, bh1);
                mma16816(acc[1][in_], al[1], bh0, bh1);
            }
        }
    }

    // ---------------- epilogue ----------------
    if (WRITE_G) {
        #pragma unroll
        for (int im = 0; im < 2; im++)
            #pragma unroll
            for (int in_ = 0; in_ < 8; in_++) {
                size_t col = colbase + n0w + in_*8 + q*2;
                int mA = mbase + m0w + im*16 + r4;
                G[col*COUT + mA]       = acc[im][in_][0];
                G[(col+1)*COUT + mA]   = acc[im][in_][1];
                G[col*COUT + mA + 8]   = acc[im][in_][2];
                G[(col+1)*COUT + mA+8] = acc[im][in_][3];
            }
    }
    #pragma unroll
    for (int im = 0; im < 2; im++) {
        float sA = 0.f, sB = 0.f, qA = 0.f, qB = 0.f;
        float mxA[2] = {-3.4e38f, -3.4e38f}, mxB[2] = {-3.4e38f, -3.4e38f};
        #pragma unroll
        for (int in_ = 0; in_ < 8; in_++) {
            int gh = in_ >> 2;
            float v0 = acc[im][in_][0], v1 = acc[im][in_][1];
            float v2 = acc[im][in_][2], v3 = acc[im][in_][3];
            sA += v0 + v1; qA += v0*v0 + v1*v1;
            sB += v2 + v3; qB += v2*v2 + v3*v3;
            mxA[gh] = fmaxf(mxA[gh], fmaxf(v0, v1));
            mxB[gh] = fmaxf(mxB[gh], fmaxf(v2, v3));
        }
        #pragma unroll
        for (int off = 1; off <= 2; off <<= 1) {
            sA += __shfl_xor_sync(0xffffffffu, sA, off);
            qA += __shfl_xor_sync(0xffffffffu, qA, off);
            sB += __shfl_xor_sync(0xffffffffu, sB, off);
            qB += __shfl_xor_sync(0xffffffffu, qB, off);
            #pragma unroll
            for (int gh = 0; gh < 2; gh++) {
                mxA[gh] = fmaxf(mxA[gh], __shfl_xor_sync(0xffffffffu, mxA[gh], off));
                mxB[gh] = fmaxf(mxB[gh], __shfl_xor_sync(0xffffffffu, mxB[gh], off));
            }
        }
        if (q == 0) {
            int lmA = m0w + im*16 + r4, lmB = lmA + 8;
            if (!WRITE_G) {
                size_t g0 = (size_t)ntile*4 + (n0w >> 5);
                Fmax[g0*COUT + mbase + lmA]     = mxA[0];
                Fmax[(g0+1)*COUT + mbase + lmA] = mxA[1];
                Fmax[g0*COUT + mbase + lmB]     = mxB[0];
                Fmax[(g0+1)*COUT + mbase + lmB] = mxB[1];
            }
            atomicAdd(&sred[lmA], sA); atomicAdd(&qred[lmA], qA);
            atomicAdd(&sred[lmB], sB); atomicAdd(&qred[lmB], qB);
        }
    }
    __syncthreads();
    if (t < 128) {
        int slot = (ntile + mtile) & (NSLOT-1);
        atomicAdd(&psum[slot*CMAX + mbase + t], (double)sred[t]);
        atomicAdd(&psq [slot*CMAX + mbase + t], (double)qred[t]);
    }
}

// ---------------- final output f2 ----------------
__global__ void k_out_f2(const float* __restrict__ Fmax, const float* __restrict__ sc,
                         const float* __restrict__ bi, float* __restrict__ out)
{
    size_t i = (size_t)blockIdx.x*256 + threadIdx.x;
    int s = (int)(i & 255);
    size_t r = i >> 8;
    int c = (int)(r & 255);
    int b = (int)(r >> 8);
    float v = Fmax[((size_t)(b*256 + s))*256 + c]*sc[c] + bi[c];
    out[24576 + i] = fmaxf(v, 0.f);
}

// ---------------- launch ----------------
extern "C" void kernel_launch(void* const* d_in, const int* in_sizes, int n_in,
                              void* d_out, int out_size)
{
    const float* x  = (const float*)d_in[0];
    const float* w1 = (const float*)d_in[1];
    const float* w2 = (const float*)d_in[2];
    const float* wa = (const float*)d_in[3];
    const float* wb = (const float*)d_in[4];
    const float* wc = (const float*)d_in[5];
    const float* wd = (const float*)d_in[6];

    void *pF0, *pF1t, *pnx1, *pfps1, *pgi1, *pF1max, *pnx2, *pfps2, *pgi2, *pF2max;
    void *pA, *pG, *ppsum, *ppsq, *pscale, *pbias;
    cudaGetSymbolAddress(&pF0, g_F0);       cudaGetSymbolAddress(&pF1t, g_F1t);
    cudaGetSymbolAddress(&pnx1, g_nx1);     cudaGetSymbolAddress(&pfps1, g_fps1);
    cudaGetSymbolAddress(&pgi1, g_gi1);     cudaGetSymbolAddress(&pF1max, g_F1max);
    cudaGetSymbolAddress(&pnx2, g_nx2);     cudaGetSymbolAddress(&pfps2, g_fps2);
    cudaGetSymbolAddress(&pgi2, g_gi2);     cudaGetSymbolAddress(&pF2max, g_F2max);
    cudaGetSymbolAddress(&pA, g_A);         cudaGetSymbolAddress(&pG, g_G);
    cudaGetSymbolAddress(&ppsum, g_psum);   cudaGetSymbolAddress(&ppsq, g_psq);
    cudaGetSymbolAddress(&pscale, g_scale); cudaGetSymbolAddress(&pbias, g_bias);

    double* psum = (double*)ppsum;
    double* psq  = (double*)ppsq;
    float* scl = (float*)pscale;
    float* bia = (float*)pbias;
    float* A = (float*)pA;
    float* G = (float*)pG;

    cudaMemsetAsync(psum, 0, 6*NSLOT*CMAX*sizeof(double), 0);
    cudaMemsetAsync(psq,  0, 6*NSLOT*CMAX*sizeof(double), 0);

    // convs + BN
    k_conv1<<<dim3(64,BB), 256>>>(x, w1, (float*)pF0, psum, psq);
    k_fin<<<1,64>>>(psum, psq, scl, bia, 64, 1.0/((double)BB*N1));
    k_conv2<<<dim3(32,BB), 256>>>((const float*)pF0, w2, scl, bia,
                                  (float*)pF1t, psum + NSLOT*CMAX, psq + NSLOT*CMAX);
    k_fin<<<1,64>>>(psum + NSLOT*CMAX, psq + NSLOT*CMAX, scl + CMAX, bia + CMAX, 64, 1.0/((double)BB*N1));

    // FPS + ball stage 1 (raw coords, x is [B,3,N] channel-major)
    k_fps<N1,S1><<<BB,256>>>(x, (size_t)3*N1, 1, N1, (int*)pfps1, (float*)pnx1);
    k_ball<<<BB*S1/4,128>>>(x, (size_t)3*N1, 1, N1, N1, (const float*)pnx1, S1, (int*)pgi1);

    // sg1
    k_gatherA<64><<<BB*S1, 256>>>((const float*)pF1t, N1, scl + CMAX, bia + CMAX,
                                  (const int*)pgi1, (const int*)pfps1, S1, A);
    k_mma<128,128,true,false><<<dim3(NT1/128,1), 256>>>(wa, A, nullptr, nullptr,
        G, nullptr, psum + 2*NSLOT*CMAX, psq + 2*NSLOT*CMAX);
    k_fin<<<1,128>>>(psum + 2*NSLOT*CMAX, psq + 2*NSLOT*CMAX, scl + 2*CMAX, bia + 2*CMAX, 128, 1.0/((double)NT1));
    k_mma<128,128,false,true><<<dim3(NT1/128,1), 256>>>(wb, G, scl + 2*CMAX, bia + 2*CMAX,
        nullptr, (float*)pF1max, psum + 3*NSLOT*CMAX, psq + 3*NSLOT*CMAX);
    k_fin<<<1,128>>>(psum + 3*NSLOT*CMAX, psq + 3*NSLOT*CMAX, scl + 3*CMAX, bia + 3*CMAX, 128, 1.0/((double)NT1));

    // FPS + ball stage 2 (nx1 is [B,S1,3] point-major)
    k_fps<S1,S2><<<BB,256>>>((const float*)pnx1, (size_t)S1*3, 3, 1, (int*)pfps2, (float*)pnx2);
    k_ball<<<BB*S2/4,128>>>((const float*)pnx1, (size_t)S1*3, 3, 1, S1, (const float*)pnx2, S2, (int*)pgi2);

    // sg2
    k_gatherA<128><<<BB*S2, 256>>>((const float*)pF1max, S1, scl + 3*CMAX, bia + 3*CMAX,
                                   (const int*)pgi2, (const int*)pfps2, S2, A);
    k_mma<256,256,true,false><<<dim3(NT2/128,2), 256>>>(wc, A, nullptr, nullptr,
        G, nullptr, psum + 4*NSLOT*CMAX, psq + 4*NSLOT*CMAX);
    k_fin<<<1,256>>>(psum + 4*NSLOT*CMAX, psq + 4*NSLOT*CMAX, scl + 4*CMAX, bia + 4*CMAX, 256, 1.0/((double)NT2));
    k_mma<256,256,false,true><<<dim3(NT2/128,2), 256>>>(wd, G, scl + 4*CMAX, bia + 4*CMAX,
        nullptr, (float*)pF2max, psum + 5*NSLOT*CMAX, psq + 5*NSLOT*CMAX);
    k_fin<<<1,256>>>(psum + 5*NSLOT*CMAX, psq + 5*NSLOT*CMAX, scl + 5*CMAX, bia + 5*CMAX, 256, 1.0/((double)NT2));

    // outputs
    cudaMemcpyAsync(d_out, pnx2, (size_t)BB*S2*3*sizeof(float), cudaMemcpyDeviceToDevice, 0);
    k_out_f2<<<(BB*256*256)/256, 256>>>((const float*)pF2max, scl + 5*CMAX, bia + 5*CMAX, (float*)d_out);
}

// round 8
// speedup vs baseline: 2.9778x; 1.1977x over previous
#include <cuda_runtime.h>
#include <cuda_bf16.h>
#include <cstdint>
#include <cstddef>

#define BB 32
#define N1 2048
#define S1 512
#define S2 256
#define NS 32
#define R2C 0.25f
#define NSLOT 32
#define CMAX 256
#define NT1 (BB*S1*NS)
#define NT2 (BB*S2*NS)
#define POOLE 67108864ull   // = NT1*128 = NT2*256

// ---------------- static device buffers ----------------
__device__ float g_F0[(size_t)BB*64*N1];
__device__ float g_F1t[(size_t)BB*N1*64];       // conv2 out, sample-major [b][n][64]
__device__ float g_nx1[(size_t)BB*S1*3];
__device__ int   g_fps1[BB*S1];
__device__ int   g_gi1[(size_t)BB*S1*NS];
__device__ float g_F1max[(size_t)BB*S1*128];
__device__ float g_nx2[(size_t)BB*S2*3];
__device__ int   g_fps2[BB*S2];
__device__ int   g_gi2[(size_t)BB*S2*NS];
__device__ float g_F2max[(size_t)BB*S2*256];

__device__ float g_A[POOLE];                    // fp32 gathered operand
__device__ float g_G[POOLE];                    // fp32 first-layer output per stage
__device__ __nv_bfloat16 g_Wh[163840];
__device__ __nv_bfloat16 g_Wl[163840];

__device__ double g_psum[6*NSLOT*CMAX];
__device__ double g_psq [6*NSLOT*CMAX];
__device__ float  g_scale[6*CMAX];
__device__ float  g_bias [6*CMAX];

// ---------------- helpers ----------------
__device__ __forceinline__ void mma16816(float* c, const uint32_t* a, uint32_t b0, uint32_t b1) {
    asm volatile("mma.sync.aligned.m16n8k16.row.col.f32.bf16.bf16.f32 "
        "{%0,%1,%2,%3}, {%4,%5,%6,%7}, {%8,%9}, {%0,%1,%2,%3};"
        : "+f"(c[0]), "+f"(c[1]), "+f"(c[2]), "+f"(c[3])
        : "r"(a[0]), "r"(a[1]), "r"(a[2]), "r"(a[3]), "r"(b0), "r"(b1));
}

#define LDSMX4(r, addr) \
    asm volatile("ldmatrix.sync.aligned.m8n8.x4.shared.b16 {%0,%1,%2,%3}, [%4];" \
        : "=r"((r)[0]), "=r"((r)[1]), "=r"((r)[2]), "=r"((r)[3]) : "r"(addr))

__device__ __forceinline__ void split4(float v0, float v1, float v2, float v3,
                                       uint2& hi, uint2& lo)
{
    __nv_bfloat162 h0 = __floats2bfloat162_rn(v0, v1);
    __nv_bfloat162 h1 = __floats2bfloat162_rn(v2, v3);
    float2 f0 = __bfloat1622float2(h0);
    float2 f1 = __bfloat1622float2(h1);
    __nv_bfloat162 l0 = __floats2bfloat162_rn(v0 - f0.x, v1 - f0.y);
    __nv_bfloat162 l1 = __floats2bfloat162_rn(v2 - f1.x, v3 - f1.y);
    hi.x = *reinterpret_cast<uint32_t*>(&h0);
    hi.y = *reinterpret_cast<uint32_t*>(&h1);
    lo.x = *reinterpret_cast<uint32_t*>(&l0);
    lo.y = *reinterpret_cast<uint32_t*>(&l1);
}

// ---------------- BN finalize ----------------
__global__ void k_fin(const double* __restrict__ psum, const double* __restrict__ psq,
                      float* __restrict__ sc, float* __restrict__ bi, int C, double invM)
{
    int t = threadIdx.x;
    if (t >= C) return;
    double s = 0.0, q = 0.0;
    for (int k = 0; k < NSLOT; k++) { s += psum[k*CMAX + t]; q += psq[k*CMAX + t]; }
    double mean = s * invM;
    double var  = q * invM - mean * mean;
    if (var < 0.0) var = 0.0;
    double sv = 1.0 / sqrt(var + 1e-5);
    sc[t] = (float)sv;
    bi[t] = (float)(-mean * sv);
}

// ---------------- weight split fp32 -> bf16 hi/lo ----------------
__global__ void k_wsplit(const float* __restrict__ src, __nv_bfloat16* __restrict__ dh,
                         __nv_bfloat16* __restrict__ dl, int n)
{
    int i = blockIdx.x*256 + threadIdx.x;
    if (i >= n) return;
    float v = src[i];
    __nv_bfloat16 h = __float2bfloat16(v);
    dh[i] = h;
    dl[i] = __float2bfloat16(v - __bfloat162float(h));
}

// ---------------- conv1 ----------------
__global__ void k_conv1(const float* __restrict__ x, const float* __restrict__ W,
                        float* __restrict__ F0, double* __restrict__ psum, double* __restrict__ psq)
{
    int c = blockIdx.x, b = blockIdx.y, t = threadIdx.x;
    float w0 = W[c*3], w1 = W[c*3+1], w2 = W[c*3+2];
    const float* xb = x + (size_t)b*3*N1;
    float* o = F0 + ((size_t)b*64 + c)*N1;
    float ls = 0.f, lq = 0.f;
    for (int n = t; n < N1; n += 256) {
        float v = w0*xb[n] + w1*xb[N1+n] + w2*xb[2*N1+n];
        o[n] = v; ls += v; lq += v*v;
    }
    for (int off = 16; off; off >>= 1) {
        ls += __shfl_down_sync(0xffffffffu, ls, off);
        lq += __shfl_down_sync(0xffffffffu, lq, off);
    }
    __shared__ float ws_[8], wq_[8];
    if ((t & 31) == 0) { ws_[t >> 5] = ls; wq_[t >> 5] = lq; }
    __syncthreads();
    if (t == 0) {
        float S = 0.f, Q = 0.f;
        for (int i = 0; i < 8; i++) { S += ws_[i]; Q += wq_[i]; }
        atomicAdd(&psum[(b & (NSLOT-1))*CMAX + c], (double)S);
        atomicAdd(&psq [(b & (NSLOT-1))*CMAX + c], (double)Q);
    }
}

// ---------------- conv2: writes F1t sample-major [b][n][64] ----------------
__global__ void k_conv2(const float* __restrict__ F0, const float* __restrict__ W,
                        const float* __restrict__ sc0, const float* __restrict__ bi0,
                        float* __restrict__ F1t, double* __restrict__ psum, double* __restrict__ psq)
{
    __shared__ float in_t[64*64];
    __shared__ float ws[64*65];
    __shared__ float pspart[4*64], pqpart[4*64];
    int tile = blockIdx.x, b = blockIdx.y, t = threadIdx.x;
    for (int i = t; i < 4096; i += 256) { int c = i >> 6, k = i & 63; ws[c*65 + k] = W[i]; }
    const float* F0b = F0 + (size_t)b*64*N1 + tile*64;
    for (int i = t; i < 4096; i += 256) {
        int k = i >> 6, nn = i & 63;
        float v = F0b[(size_t)k*N1 + nn]*sc0[k] + bi0[k];
        in_t[k*64 + nn] = fmaxf(v, 0.f);
    }
    __syncthreads();
    int c = t & 63, nq = t >> 6;
    float acc[16];
    #pragma unroll
    for (int j = 0; j < 16; j++) acc[j] = 0.f;
    for (int k = 0; k < 64; k++) {
        float wv = ws[c*65 + k];
        const float* ar = &in_t[k*64 + nq*16];
        #pragma unroll
        for (int jq = 0; jq < 4; jq++) {
            float4 a = *(const float4*)(ar + 4*jq);
            acc[4*jq+0] += wv*a.x; acc[4*jq+1] += wv*a.y;
            acc[4*jq+2] += wv*a.z; acc[4*jq+3] += wv*a.w;
        }
    }
    float lsum = 0.f, lsq = 0.f;
    #pragma unroll
    for (int j = 0; j < 16; j++) { float v = acc[j]; lsum += v; lsq += v*v; }
    pspart[nq*64 + c] = lsum; pqpart[nq*64 + c] = lsq;
    __syncthreads();
    #pragma unroll
    for (int j = 0; j < 16; j++) ws[(nq*16 + j)*65 + c] = acc[j];
    if (t < 64) {
        float s = pspart[t] + pspart[64+t] + pspart[128+t] + pspart[192+t];
        float q = pqpart[t] + pqpart[64+t] + pqpart[128+t] + pqpart[192+t];
        int slot = (blockIdx.x + 32*blockIdx.y) & (NSLOT-1);
        atomicAdd(&psum[slot*CMAX + t], (double)s);
        atomicAdd(&psq [slot*CMAX + t], (double)q);
    }
    __syncthreads();
    size_t nbase = (size_t)b*N1 + tile*64;
    for (int i = t; i < 4096; i += 256) {
        int n = i >> 6, cc = i & 63;
        F1t[(nbase + n)*64 + cc] = ws[n*65 + cc];
    }
}

// ---------------- FPS ----------------
template<int N, int S>
__global__ void __launch_bounds__(256) k_fps(const float* __restrict__ P, size_t bstride,
                      size_t pstride, size_t cstride,
                      int* __restrict__ outIdx, float* __restrict__ outXYZ)
{
    int b = blockIdx.x, t = threadIdx.x, wid = t >> 5, lane = t & 31;
    const float* Pb = P + (size_t)b*bstride;
    __shared__ float xs[N], ys[N], zs[N], dist[N];
    __shared__ float wv[8]; __shared__ int wi[8]; __shared__ int sfar;
    for (int j = t; j < N; j += 256) {
        xs[j] = Pb[(size_t)j*pstride];
        ys[j] = Pb[(size_t)j*pstride + cstride];
        zs[j] = Pb[(size_t)j*pstride + 2*cstride];
        dist[j] = 1e10f;
    }
    if (t == 0) sfar = 0;
    __syncthreads();
    for (int s = 0; s < S; s++) {
        int far = sfar;
        float fx = xs[far], fy = ys[far], fz = zs[far];
        if (t == 0) {
            outIdx[(size_t)b*S + s] = far;
            float* o = &outXYZ[((size_t)b*S + s)*3];
            o[0] = fx; o[1] = fy; o[2] = fz;
        }
        float bv = -1.f; int bi = 0x7fffffff;
        for (int j = t; j < N; j += 256) {
            float dx = __fsub_rn(xs[j], fx);
            float dy = __fsub_rn(ys[j], fy);
            float dz = __fsub_rn(zs[j], fz);
            float d = __fadd_rn(__fadd_rn(__fmul_rn(dx,dx), __fmul_rn(dy,dy)), __fmul_rn(dz,dz));
            float nd = fminf(dist[j], d);
            dist[j] = nd;
            if (nd > bv) { bv = nd; bi = j; }
        }
        #pragma unroll
        for (int off = 16; off; off >>= 1) {
            float ov = __shfl_down_sync(0xffffffffu, bv, off);
            int   oi = __shfl_down_sync(0xffffffffu, bi, off);
            if (ov > bv || (ov == bv && oi < bi)) { bv = ov; bi = oi; }
        }
        if (lane == 0) { wv[wid] = bv; wi[wid] = bi; }
        __syncthreads();
        if (t == 0) {
            float best = wv[0]; int besti = wi[0];
            #pragma unroll
            for (int k = 1; k < 8; k++)
                if (wv[k] > best || (wv[k] == best && wi[k] < besti)) { best = wv[k]; besti = wi[k]; }
            sfar = besti;
        }
        __syncthreads();
    }
}

// ---------------- ball query ----------------
__global__ void k_ball(const float* __restrict__ C, size_t bstrideC, size_t pstride, size_t cstride,
                       int N, const float* __restrict__ Q, int S, int* __restrict__ gi)
{
    int wid = threadIdx.x >> 5, lane = threadIdx.x & 31;
    int g = blockIdx.x*4 + wid;
    int b = g / S;
    const float* Cb = C + (size_t)b*bstrideC;
    const float* q = Q + (size_t)g*3;
    float qx = q[0], qy = q[1], qz = q[2];
    __shared__ int buf[4][NS];
    int cnt = 0;
    for (int base = 0; base < N && cnt < NS; base += 32) {
        int j = base + lane;
        float dx = __fsub_rn(Cb[(size_t)j*pstride], qx);
        float dy = __fsub_rn(Cb[(size_t)j*pstride + cstride], qy);
        float dz = __fsub_rn(Cb[(size_t)j*pstride + 2*cstride], qz);
        float d = __fadd_rn(__fadd_rn(__fmul_rn(dx,dx), __fmul_rn(dy,dy)), __fmul_rn(dz,dz));
        bool ok = !(d > R2C);
        unsigned m = __ballot_sync(0xffffffffu, ok);
        int pos = cnt + __popc(m & ((1u << lane) - 1u));
        if (ok && pos < NS) buf[wid][pos] = j;
        cnt += __popc(m);
    }
    __syncwarp();
    int first = buf[wid][0];
    int mm = cnt < NS ? cnt : NS;
    int v = (lane < mm) ? buf[wid][lane] : first;
    gi[(size_t)g*NS + lane] = v;
}

// ---------------- gather: build A fp32, [col][CIN] K-major ----------------
template<int CH>
__global__ void __launch_bounds__(256) k_gatherA(
    const float* __restrict__ src, int NP,
    const float* __restrict__ sc, const float* __restrict__ bi,
    const int* __restrict__ gi, const int* __restrict__ fpsidx, int S,
    float* __restrict__ A)
{
    constexpr int CIN = 2*CH;
    __shared__ float fc[CH]; __shared__ int gix[32];
    int g = blockIdx.x, t = threadIdx.x, wid = t >> 5, lane = t & 31;
    int b = g / S, s = g % S;
    if (t < 32) gix[t] = gi[(size_t)g*NS + t];
    if (t < CH) {
        int ci = fpsidx[(size_t)b*S + s];
        float v = src[((size_t)b*NP + ci)*CH + t]*sc[t] + bi[t];
        fc[t] = fmaxf(v, 0.f);
    }
    __syncthreads();
    for (int k = wid; k < NS; k += 8) {
        size_t row = (size_t)b*NP + gix[k];
        size_t ob = ((size_t)g*NS + k)*CIN;
        for (int c = lane; c < CH; c += 32) {
            float v = src[row*CH + c]*sc[c] + bi[c];
            v = fmaxf(v, 0.f);
            A[ob + c]      = v - fc[c];
            A[ob + CH + c] = fc[c];
        }
    }
}

// ---------------- mma.sync GEMM: ldmatrix fragments + in-kernel A split ----------------
// C[128,128] tile = W[128,K] x A[cols,K]^T, 3-term split: WhAh + WhAl + WlAh
template<int K, int COUT, bool WRITE_G, bool BN>
__global__ void __launch_bounds__(256, 2) k_mma(
    const __nv_bfloat16* __restrict__ Wh, const __nv_bfloat16* __restrict__ Wl,
    const float* __restrict__ A,
    const float* __restrict__ bnsc, const float* __restrict__ bnbi,
    float* __restrict__ G, float* __restrict__ Fmax,
    double* __restrict__ psum, double* __restrict__ psq)
{
    __shared__ __align__(16) __nv_bfloat16 Wht[128*40];
    __shared__ __align__(16) __nv_bfloat16 Wlt[128*40];
    __shared__ __align__(16) __nv_bfloat16 Aht[128*40];
    __shared__ __align__(16) __nv_bfloat16 Alt[128*40];
    __shared__ float sred[128], qred[128];
    __shared__ float scs[256], bis[256];

    int t = threadIdx.x, wid = t >> 5, lane = t & 31;
    int r4 = lane >> 2, q = lane & 3;
    int ntile = blockIdx.x, mtile = blockIdx.y;
    size_t colbase = (size_t)ntile*128;
    int mbase = mtile*128;
    int m0w = (wid & 3)*32, n0w = (wid >> 2)*64;

    for (int i = t; i < 128; i += 256) { sred[i] = 0.f; qred[i] = 0.f; }
    if (BN) for (int i = t; i < K; i += 256) { scs[i] = bnsc[i]; bis[i] = bnbi[i]; }

    float acc[2][8][4];
    #pragma unroll
    for (int im = 0; im < 2; im++)
        #pragma unroll
        for (int in_ = 0; in_ < 8; in_++)
            #pragma unroll
            for (int c = 0; c < 4; c++) acc[im][in_][c] = 0.f;

    constexpr int NCH = K/32;

    // ldmatrix per-lane base offsets (bytes)
    uint32_t whtB = (uint32_t)__cvta_generic_to_shared(Wht);
    uint32_t wltB = (uint32_t)__cvta_generic_to_shared(Wlt);
    uint32_t ahtB = (uint32_t)__cvta_generic_to_shared(Aht);
    uint32_t altB = (uint32_t)__cvta_generic_to_shared(Alt);
    uint32_t aOff = (uint32_t)(((m0w + (lane & 15))*40 + (lane >> 4)*8)*2);
    uint32_t bOff = (uint32_t)(((((lane & 7) + ((lane >> 4) << 3)) + n0w)*40 + ((lane >> 3) & 1)*8)*2);

    uint4 pa[4];
    #pragma unroll
    for (int i = 0; i < 4; i++) {
        int idx = t + 256*i, row = idx >> 3, seg = idx & 7;
        pa[i] = *(const uint4*)(A + (colbase + row)*(size_t)K + seg*4);
    }

    #pragma unroll 1
    for (int kc = 0; kc < NCH; kc++) {
        __syncthreads();
        // store A chunk (convert, optional BN+relu)
        #pragma unroll
        for (int i = 0; i < 4; i++) {
            int idx = t + 256*i, row = idx >> 3, seg = idx & 7;
            float4 f = *(float4*)&pa[i];
            if (BN) {
                int kb = kc*32 + seg*4;
                f.x = fmaxf(f.x*scs[kb]   + bis[kb],   0.f);
                f.y = fmaxf(f.y*scs[kb+1] + bis[kb+1], 0.f);
                f.z = fmaxf(f.z*scs[kb+2] + bis[kb+2], 0.f);
                f.w = fmaxf(f.w*scs[kb+3] + bis[kb+3], 0.f);
            }
            uint2 hi, lo;
            split4(f.x, f.y, f.z, f.w, hi, lo);
            *(uint2*)&Aht[row*40 + seg*4] = hi;
            *(uint2*)&Alt[row*40 + seg*4] = lo;
        }
        // copy W chunk (bf16 hi/lo, precomputed)
        #pragma unroll
        for (int i = 0; i < 2; i++) {
            int idx = t + 256*i, row = idx >> 2, seg = idx & 3;
            *(uint4*)&Wht[row*40 + seg*8] =
                *(const uint4*)(Wh + (size_t)(mbase + row)*K + kc*32 + seg*8);
            *(uint4*)&Wlt[row*40 + seg*8] =
                *(const uint4*)(Wl + (size_t)(mbase + row)*K + kc*32 + seg*8);
        }
        __syncthreads();
        if (kc + 1 < NCH) {
            #pragma unroll
            for (int i = 0; i < 4; i++) {
                int idx = t + 256*i, row = idx >> 3, seg = idx & 7;
                pa[i] = *(const uint4*)(A + (colbase + row)*(size_t)K + (kc+1)*32 + seg*4);
            }
        }
        #pragma unroll
        for (int kk = 0; kk < 2; kk++) {
            uint32_t akk = aOff + kk*32;
            uint32_t ah0[4], ah1[4], al0[4], al1[4];
            LDSMX4(ah0, whtB + akk);
            LDSMX4(ah1, whtB + akk + 1280);
            LDSMX4(al0, wltB + akk);
            LDSMX4(al1, wltB + akk + 1280);
            #pragma unroll
            for (int inp = 0; inp < 4; inp++) {
                uint32_t bkk = bOff + (uint32_t)((inp*16*40 + kk*16)*2);
                uint32_t bh[4], bl[4];
                LDSMX4(bh, ahtB + bkk);
                LDSMX4(bl, altB + bkk);
                mma16816(acc[0][2*inp],   ah0, bh[0], bh[1]);
                mma16816(acc[1][2*inp],   ah1, bh[0], bh[1]);
                mma16816(acc[0][2*inp],   ah0, bl[0], bl[1]);
                mma16816(acc[1][2*inp],   ah1, bl[0], bl[1]);
                mma16816(acc[0][2*inp],   al0, bh[0], bh[1]);
                mma16816(acc[1][2*inp],   al1, bh[0], bh[1]);
                mma16816(acc[0][2*inp+1], ah0, bh[2], bh[3]);
                mma16816(acc[1][2*inp+1], ah1, bh[2], bh[3]);
                mma16816(acc[0][2*inp+1], ah0, bl[2], bl[3]);
                mma16816(acc[1][2*inp+1], ah1, bl[2], bl[3]);
                mma16816(acc[0][2*inp+1], al0, bh[2], bh[3]);
                mma16816(acc[1][2*inp+1], al1, bh[2], bh[3]);
            }
        }
    }

    // ---------------- epilogue ----------------
    if (WRITE_G) {
        #pragma unroll
        for (int im = 0; im < 2; im++)
            #pragma unroll
            for (int in_ = 0; in_ < 8; in_++) {
                size_t col = colbase + n0w + in_*8 + q*2;
                int mA = mbase + m0w + im*16 + r4;
                G[col*COUT + mA]       = acc[im][in_][0];
                G[(col+1)*COUT + mA]   = acc[im][in_][1];
                G[col*COUT + mA + 8]   = acc[im][in_][2];
                G[(col+1)*COUT + mA+8] = acc[im][in_][3];
            }
    }
    #pragma unroll
    for (int im = 0; im < 2; im++) {
        float sA = 0.f, sB = 0.f, qA = 0.f, qB = 0.f;
        float mxA[2] = {-3.4e38f, -3.4e38f}, mxB[2] = {-3.4e38f, -3.4e38f};
        #pragma unroll
        for (int in_ = 0; in_ < 8; in_++) {
            int gh = in_ >> 2;
            float v0 = acc[im][in_][0], v1 = acc[im][in_][1];
            float v2 = acc[im][in_][2], v3 = acc[im][in_][3];
            sA += v0 + v1; qA += v0*v0 + v1*v1;
            sB += v2 + v3; qB += v2*v2 + v3*v3;
            mxA[gh] = fmaxf(mxA[gh], fmaxf(v0, v1));
            mxB[gh] = fmaxf(mxB[gh], fmaxf(v2, v3));
        }
        #pragma unroll
        for (int off = 1; off <= 2; off <<= 1) {
            sA += __shfl_xor_sync(0xffffffffu, sA, off);
            qA += __shfl_xor_sync(0xffffffffu, qA, off);
            sB += __shfl_xor_sync(0xffffffffu, sB, off);
            qB += __shfl_xor_sync(0xffffffffu, qB, off);
            #pragma unroll
            for (int gh = 0; gh < 2; gh++) {
                mxA[gh] = fmaxf(mxA[gh], __shfl_xor_sync(0xffffffffu, mxA[gh], off));
                mxB[gh] = fmaxf(mxB[gh], __shfl_xor_sync(0xffffffffu, mxB[gh], off));
            }
        }
        if (q == 0) {
            int lmA = m0w + im*16 + r4, lmB = lmA + 8;
            if (!WRITE_G) {
                size_t g0 = (size_t)ntile*4 + (n0w >> 5);
                Fmax[g0*COUT + mbase + lmA]     = mxA[0];
                Fmax[(g0+1)*COUT + mbase + lmA] = mxA[1];
                Fmax[g0*COUT + mbase + lmB]     = mxB[0];
                Fmax[(g0+1)*COUT + mbase + lmB] = mxB[1];
            }
            atomicAdd(&sred[lmA], sA); atomicAdd(&qred[lmA], qA);
            atomicAdd(&sred[lmB], sB); atomicAdd(&qred[lmB], qB);
        }
    }
    __syncthreads();
    if (t < 128) {
        int slot = (ntile + mtile) & (NSLOT-1);
        atomicAdd(&psum[slot*CMAX + mbase + t], (double)sred[t]);
        atomicAdd(&psq [slot*CMAX + mbase + t], (double)qred[t]);
    }
}

// ---------------- final output f2 ----------------
__global__ void k_out_f2(const float* __restrict__ Fmax, const float* __restrict__ sc,
                         const float* __restrict__ bi, float* __restrict__ out)
{
    size_t i = (size_t)blockIdx.x*256 + threadIdx.x;
    int s = (int)(i & 255);
    size_t r = i >> 8;
    int c = (int)(r & 255);
    int b = (int)(r >> 8);
    float v = Fmax[((size_t)(b*256 + s))*256 + c]*sc[c] + bi[c];
    out[24576 + i] = fmaxf(v, 0.f);
}

// ---------------- launch ----------------
extern "C" void kernel_launch(void* const* d_in, const int* in_sizes, int n_in,
                              void* d_out, int out_size)
{
    const float* x  = (const float*)d_in[0];
    const float* w1 = (const float*)d_in[1];
    const float* w2 = (const float*)d_in[2];
    const float* wa = (const float*)d_in[3];
    const float* wb = (const float*)d_in[4];
    const float* wc = (const float*)d_in[5];
    const float* wd = (const float*)d_in[6];

    void *pF0, *pF1t, *pnx1, *pfps1, *pgi1, *pF1max, *pnx2, *pfps2, *pgi2, *pF2max;
    void *pA, *pG, *pWh, *pWl, *ppsum, *ppsq, *pscale, *pbias;
    cudaGetSymbolAddress(&pF0, g_F0);       cudaGetSymbolAddress(&pF1t, g_F1t);
    cudaGetSymbolAddress(&pnx1, g_nx1);     cudaGetSymbolAddress(&pfps1, g_fps1);
    cudaGetSymbolAddress(&pgi1, g_gi1);     cudaGetSymbolAddress(&pF1max, g_F1max);
    cudaGetSymbolAddress(&pnx2, g_nx2);     cudaGetSymbolAddress(&pfps2, g_fps2);
    cudaGetSymbolAddress(&pgi2, g_gi2);     cudaGetSymbolAddress(&pF2max, g_F2max);
    cudaGetSymbolAddress(&pA, g_A);         cudaGetSymbolAddress(&pG, g_G);
    cudaGetSymbolAddress(&pWh, g_Wh);       cudaGetSymbolAddress(&pWl, g_Wl);
    cudaGetSymbolAddress(&ppsum, g_psum);   cudaGetSymbolAddress(&ppsq, g_psq);
    cudaGetSymbolAddress(&pscale, g_scale); cudaGetSymbolAddress(&pbias, g_bias);

    double* psum = (double*)ppsum;
    double* psq  = (double*)ppsq;
    float* scl = (float*)pscale;
    float* bia = (float*)pbias;
    float* A = (float*)pA;
    float* G = (float*)pG;
    __nv_bfloat16* Wh = (__nv_bfloat16*)pWh;
    __nv_bfloat16* Wl = (__nv_bfloat16*)pWl;

    cudaMemsetAsync(psum, 0, 6*NSLOT*CMAX*sizeof(double), 0);
    cudaMemsetAsync(psq,  0, 6*NSLOT*CMAX*sizeof(double), 0);

    // weight splits (tiny, one-time per launch)
    k_wsplit<<<64,256>>>(wa, Wh + 0,      Wl + 0,      16384);
    k_wsplit<<<64,256>>>(wb, Wh + 16384,  Wl + 16384,  16384);
    k_wsplit<<<256,256>>>(wc, Wh + 32768, Wl + 32768,  65536);
    k_wsplit<<<256,256>>>(wd, Wh + 98304, Wl + 98304,  65536);

    // convs + BN
    k_conv1<<<dim3(64,BB), 256>>>(x, w1, (float*)pF0, psum, psq);
    k_fin<<<1,64>>>(psum, psq, scl, bia, 64, 1.0/((double)BB*N1));
    k_conv2<<<dim3(32,BB), 256>>>((const float*)pF0, w2, scl, bia,
                                  (float*)pF1t, psum + NSLOT*CMAX, psq + NSLOT*CMAX);
    k_fin<<<1,64>>>(psum + NSLOT*CMAX, psq + NSLOT*CMAX, scl + CMAX, bia + CMAX, 64, 1.0/((double)BB*N1));

    // FPS + ball stage 1 (raw coords, x is [B,3,N] channel-major)
    k_fps<N1,S1><<<BB,256>>>(x, (size_t)3*N1, 1, N1, (int*)pfps1, (float*)pnx1);
    k_ball<<<BB*S1/4,128>>>(x, (size_t)3*N1, 1, N1, N1, (const float*)pnx1, S1, (int*)pgi1);

    // sg1
    k_gatherA<64><<<BB*S1, 256>>>((const float*)pF1t, N1, scl + CMAX, bia + CMAX,
                                  (const int*)pgi1, (const int*)pfps1, S1, A);
    k_mma<128,128,true,false><<<dim3(NT1/128,1), 256>>>(Wh + 0, Wl + 0, A, nullptr, nullptr,
        G, nullptr, psum + 2*NSLOT*CMAX, psq + 2*NSLOT*CMAX);
    k_fin<<<1,128>>>(psum + 2*NSLOT*CMAX, psq + 2*NSLOT*CMAX, scl + 2*CMAX, bia + 2*CMAX, 128, 1.0/((double)NT1));
    k_mma<128,128,false,true><<<dim3(NT1/128,1), 256>>>(Wh + 16384, Wl + 16384, G,
        scl + 2*CMAX, bia + 2*CMAX,
        nullptr, (float*)pF1max, psum + 3*NSLOT*CMAX, psq + 3*NSLOT*CMAX);
    k_fin<<<1,128>>>(psum + 3*NSLOT*CMAX, psq + 3*NSLOT*CMAX, scl + 3*CMAX, bia + 3*CMAX, 128, 1.0/((double)NT1));

    // FPS + ball stage 2 (nx1 is [B,S1,3] point-major)
    k_fps<S1,S2><<<BB,256>>>((const float*)pnx1, (size_t)S1*3, 3, 1, (int*)pfps2, (float*)pnx2);
    k_ball<<<BB*S2/4,128>>>((const float*)pnx1, (size_t)S1*3, 3, 1, S1, (const float*)pnx2, S2, (int*)pgi2);

    // sg2
    k_gatherA<128><<<BB*S2, 256>>>((const float*)pF1max, S1, scl + 3*CMAX, bia + 3*CMAX,
                                   (const int*)pgi2, (const int*)pfps2, S2, A);
    k_mma<256,256,true,false><<<dim3(NT2/128,2), 256>>>(Wh + 32768, Wl + 32768, A, nullptr, nullptr,
        G, nullptr, psum + 4*NSLOT*CMAX, psq + 4*NSLOT*CMAX);
    k_fin<<<1,256>>>(psum + 4*NSLOT*CMAX, psq + 4*NSLOT*CMAX, scl + 4*CMAX, bia + 4*CMAX, 256, 1.0/((double)NT2));
    k_mma<256,256,false,true><<<dim3(NT2/128,2), 256>>>(Wh + 98304, Wl + 98304, G,
        scl + 4*CMAX, bia + 4*CMAX,
        nullptr, (float*)pF2max, psum + 5*NSLOT*CMAX, psq + 5*NSLOT*CMAX);
    k_fin<<<1,256>>>(psum + 5*NSLOT*CMAX, psq + 5*NSLOT*CMAX, scl + 5*CMAX, bia + 5*CMAX, 256, 1.0/((double)NT2));

    // outputs
    cudaMemcpyAsync(d_out, pnx2, (size_t)BB*S2*3*sizeof(float), cudaMemcpyDeviceToDevice, 0);
    k_out_f2<<<(BB*256*256)/256, 256>>>((const float*)pF2max, scl + 5*CMAX, bia + 5*CMAX, (float*)d_out);
}

// round 9
// speedup vs baseline: 3.0777x; 1.0335x over previous
#include <cuda_runtime.h>
#include <cuda_bf16.h>
#include <cstdint>
#include <cstddef>

#define BB 32
#define N1 2048
#define S1 512
#define S2 256
#define NS 32
#define R2C 0.25f
#define NSLOT 32
#define CMAX 256
#define NT1 (BB*S1*NS)
#define NT2 (BB*S2*NS)
#define POOLE 67108864ull

// ---------------- static device buffers ----------------
__device__ float g_F0[(size_t)BB*64*N1];
__device__ float g_F1t[(size_t)BB*N1*64];
__device__ float g_nx1[(size_t)BB*S1*3];
__device__ int   g_fps1[BB*S1];
__device__ int   g_gi1[(size_t)BB*S1*NS];
__device__ float g_F1max[(size_t)BB*S1*128];
__device__ float g_nx2[(size_t)BB*S2*3];
__device__ int   g_fps2[BB*S2];
__device__ int   g_gi2[(size_t)BB*S2*NS];
__device__ float g_F2max[(size_t)BB*S2*256];

__device__ __nv_bfloat16 g_Ah[POOLE];
__device__ __nv_bfloat16 g_Al[POOLE];
__device__ float g_G[POOLE];
__device__ __nv_bfloat16 g_Wh[163840];
__device__ __nv_bfloat16 g_Wl[163840];

__device__ double g_psum[6*NSLOT*CMAX];
__device__ double g_psq [6*NSLOT*CMAX];
__device__ float  g_scale[6*CMAX];
__device__ float  g_bias [6*CMAX];
__device__ int    g_ctr[8];

// ---------------- helpers ----------------
__device__ __forceinline__ void mma16816(float* c, const uint32_t* a, uint32_t b0, uint32_t b1) {
    asm volatile("mma.sync.aligned.m16n8k16.row.col.f32.bf16.bf16.f32 "
        "{%0,%1,%2,%3}, {%4,%5,%6,%7}, {%8,%9}, {%0,%1,%2,%3};"
        : "+f"(c[0]), "+f"(c[1]), "+f"(c[2]), "+f"(c[3])
        : "r"(a[0]), "r"(a[1]), "r"(a[2]), "r"(a[3]), "r"(b0), "r"(b1));
}

#define LDSMX4(r, addr) \
    asm volatile("ldmatrix.sync.aligned.m8n8.x4.shared.b16 {%0,%1,%2,%3}, [%4];" \
        : "=r"((r)[0]), "=r"((r)[1]), "=r"((r)[2]), "=r"((r)[3]) : "r"(addr))

__device__ __forceinline__ void split2(float a, float b, uint32_t& hi, uint32_t& lo)
{
    __nv_bfloat162 h = __floats2bfloat162_rn(a, b);
    float2 f = __bfloat1622float2(h);
    __nv_bfloat162 l = __floats2bfloat162_rn(a - f.x, b - f.y);
    hi = *reinterpret_cast<uint32_t*>(&h);
    lo = *reinterpret_cast<uint32_t*>(&l);
}
__device__ __forceinline__ void split4(float v0, float v1, float v2, float v3,
                                       uint2& hi, uint2& lo)
{
    split2(v0, v1, hi.x, lo.x);
    split2(v2, v3, hi.y, lo.y);
}

// finalize BN stats for channel t (call from last CTA only)
__device__ __forceinline__ void bn_finalize(const double* psum, const double* psq,
                                            float* sc, float* bi, int t, double invM)
{
    double s = 0.0, q = 0.0;
    for (int k = 0; k < NSLOT; k++) {
        s += __ldcg(&psum[k*CMAX + t]);
        q += __ldcg(&psq [k*CMAX + t]);
    }
    double mean = s * invM;
    double var  = q * invM - mean * mean;
    if (var < 0.0) var = 0.0;
    double sv = 1.0 / sqrt(var + 1e-5);
    sc[t] = (float)sv;
    bi[t] = (float)(-mean * sv);
}

// ---------------- weight split ----------------
__global__ void k_wsplit(const float* __restrict__ src, __nv_bfloat16* __restrict__ dh,
                         __nv_bfloat16* __restrict__ dl, int n)
{
    int i = blockIdx.x*256 + threadIdx.x;
    if (i >= n) return;
    float v = src[i];
    __nv_bfloat16 h = __float2bfloat16(v);
    dh[i] = h;
    dl[i] = __float2bfloat16(v - __bfloat162float(h));
}

// ---------------- conv1 (finalizes BN0 in last CTA) ----------------
__global__ void k_conv1(const float* __restrict__ x, const float* __restrict__ W,
                        float* __restrict__ F0, double* __restrict__ psum, double* __restrict__ psq,
                        int* __restrict__ ctr, float* __restrict__ osc, float* __restrict__ obi)
{
    int c = blockIdx.x, b = blockIdx.y, t = threadIdx.x;
    float w0 = W[c*3], w1 = W[c*3+1], w2 = W[c*3+2];
    const float* xb = x + (size_t)b*3*N1;
    float* o = F0 + ((size_t)b*64 + c)*N1;
    float ls = 0.f, lq = 0.f;
    for (int n = t; n < N1; n += 256) {
        float v = w0*xb[n] + w1*xb[N1+n] + w2*xb[2*N1+n];
        o[n] = v; ls += v; lq += v*v;
    }
    for (int off = 16; off; off >>= 1) {
        ls += __shfl_down_sync(0xffffffffu, ls, off);
        lq += __shfl_down_sync(0xffffffffu, lq, off);
    }
    __shared__ float ws_[8], wq_[8];
    __shared__ int lastf;
    if ((t & 31) == 0) { ws_[t >> 5] = ls; wq_[t >> 5] = lq; }
    __syncthreads();
    if (t == 0) {
        float S = 0.f, Q = 0.f;
        for (int i = 0; i < 8; i++) { S += ws_[i]; Q += wq_[i]; }
        atomicAdd(&psum[(b & (NSLOT-1))*CMAX + c], (double)S);
        atomicAdd(&psq [(b & (NSLOT-1))*CMAX + c], (double)Q);
        __threadfence();
        lastf = (atomicAdd(ctr, 1) == 64*BB - 1) ? 1 : 0;
    }
    __syncthreads();
    if (lastf && t < 64) bn_finalize(psum, psq, osc, obi, t, 1.0/((double)BB*N1));
}

// ---------------- conv2 (finalizes BN1) ----------------
__global__ void k_conv2(const float* __restrict__ F0, const float* __restrict__ W,
                        const float* __restrict__ sc0, const float* __restrict__ bi0,
                        float* __restrict__ F1t, double* __restrict__ psum, double* __restrict__ psq,
                        int* __restrict__ ctr, float* __restrict__ osc, float* __restrict__ obi)
{
    __shared__ float in_t[64*64];
    __shared__ float ws[64*65];
    __shared__ float pspart[4*64], pqpart[4*64];
    __shared__ int lastf;
    int tile = blockIdx.x, b = blockIdx.y, t = threadIdx.x;
    for (int i = t; i < 4096; i += 256) { int c = i >> 6, k = i & 63; ws[c*65 + k] = W[i]; }
    const float* F0b = F0 + (size_t)b*64*N1 + tile*64;
    for (int i = t; i < 4096; i += 256) {
        int k = i >> 6, nn = i & 63;
        float v = F0b[(size_t)k*N1 + nn]*sc0[k] + bi0[k];
        in_t[k*64 + nn] = fmaxf(v, 0.f);
    }
    __syncthreads();
    int c = t & 63, nq = t >> 6;
    float acc[16];
    #pragma unroll
    for (int j = 0; j < 16; j++) acc[j] = 0.f;
    for (int k = 0; k < 64; k++) {
        float wv = ws[c*65 + k];
        const float* ar = &in_t[k*64 + nq*16];
        #pragma unroll
        for (int jq = 0; jq < 4; jq++) {
            float4 a = *(const float4*)(ar + 4*jq);
            acc[4*jq+0] += wv*a.x; acc[4*jq+1] += wv*a.y;
            acc[4*jq+2] += wv*a.z; acc[4*jq+3] += wv*a.w;
        }
    }
    float lsum = 0.f, lsq = 0.f;
    #pragma unroll
    for (int j = 0; j < 16; j++) { float v = acc[j]; lsum += v; lsq += v*v; }
    pspart[nq*64 + c] = lsum; pqpart[nq*64 + c] = lsq;
    __syncthreads();
    #pragma unroll
    for (int j = 0; j < 16; j++) ws[(nq*16 + j)*65 + c] = acc[j];
    if (t < 64) {
        float s = pspart[t] + pspart[64+t] + pspart[128+t] + pspart[192+t];
        float q = pqpart[t] + pqpart[64+t] + pqpart[128+t] + pqpart[192+t];
        int slot = (blockIdx.x + 32*blockIdx.y) & (NSLOT-1);
        atomicAdd(&psum[slot*CMAX + t], (double)s);
        atomicAdd(&psq [slot*CMAX + t], (double)q);
    }
    __syncthreads();
    size_t nbase = (size_t)b*N1 + tile*64;
    for (int i = t; i < 4096; i += 256) {
        int n = i >> 6, cc = i & 63;
        F1t[(nbase + n)*64 + cc] = ws[n*65 + cc];
    }
    if (t == 0) {
        __threadfence();
        lastf = (atomicAdd(ctr, 1) == 32*BB - 1) ? 1 : 0;
    }
    __syncthreads();
    if (lastf && t < 64) bn_finalize(psum, psq, osc, obi, t, 1.0/((double)BB*N1));
}

// ---------------- FPS: register dist, one sync per iter ----------------
template<int N, int S>
__global__ void __launch_bounds__(256) k_fps(const float* __restrict__ P, size_t bstride,
                      size_t pstride, size_t cstride,
                      int* __restrict__ outIdx, float* __restrict__ outXYZ)
{
    constexpr int PPT = N/256;
    int b = blockIdx.x, t = threadIdx.x, wid = t >> 5, lane = t & 31;
    const float* Pb = P + (size_t)b*bstride;
    __shared__ float xs[N], ys[N], zs[N];
    __shared__ float wv[2][8]; __shared__ int wi[2][8];
    for (int j = t; j < N; j += 256) {
        xs[j] = Pb[(size_t)j*pstride];
        ys[j] = Pb[(size_t)j*pstride + cstride];
        zs[j] = Pb[(size_t)j*pstride + 2*cstride];
    }
    float dist[PPT];
    #pragma unroll
    for (int i = 0; i < PPT; i++) dist[i] = 1e10f;
    __syncthreads();
    int far = 0;
    for (int s = 0; s < S; s++) {
        float fx = xs[far], fy = ys[far], fz = zs[far];
        if (t == 0) {
            outIdx[(size_t)b*S + s] = far;
            float* o = &outXYZ[((size_t)b*S + s)*3];
            o[0] = fx; o[1] = fy; o[2] = fz;
        }
        float bv = -1.f; int bi = 0x7fffffff;
        #pragma unroll
        for (int i = 0; i < PPT; i++) {
            int j = i*256 + t;
            float dx = __fsub_rn(xs[j], fx);
            float dy = __fsub_rn(ys[j], fy);
            float dz = __fsub_rn(zs[j], fz);
            float d = __fadd_rn(__fadd_rn(__fmul_rn(dx,dx), __fmul_rn(dy,dy)), __fmul_rn(dz,dz));
            float nd = fminf(dist[i], d);
            dist[i] = nd;
            if (nd > bv) { bv = nd; bi = j; }
        }
        #pragma unroll
        for (int off = 16; off; off >>= 1) {
            float ov = __shfl_down_sync(0xffffffffu, bv, off);
            int   oi = __shfl_down_sync(0xffffffffu, bi, off);
            if (ov > bv || (ov == bv && oi < bi)) { bv = ov; bi = oi; }
        }
        int p = s & 1;
        if (lane == 0) { wv[p][wid] = bv; wi[p][wid] = bi; }
        __syncthreads();
        float best = wv[p][0]; int besti = wi[p][0];
        #pragma unroll
        for (int k = 1; k < 8; k++) {
            float v2 = wv[p][k]; int i2 = wi[p][k];
            if (v2 > best || (v2 == best && i2 < besti)) { best = v2; besti = i2; }
        }
        far = besti;
    }
}

// ---------------- ball query ----------------
__global__ void k_ball(const float* __restrict__ C, size_t bstrideC, size_t pstride, size_t cstride,
                       int N, const float* __restrict__ Q, int S, int* __restrict__ gi)
{
    int wid = threadIdx.x >> 5, lane = threadIdx.x & 31;
    int g = blockIdx.x*4 + wid;
    int b = g / S;
    const float* Cb = C + (size_t)b*bstrideC;
    const float* q = Q + (size_t)g*3;
    float qx = q[0], qy = q[1], qz = q[2];
    __shared__ int buf[4][NS];
    int cnt = 0;
    for (int base = 0; base < N && cnt < NS; base += 32) {
        int j = base + lane;
        float dx = __fsub_rn(Cb[(size_t)j*pstride], qx);
        float dy = __fsub_rn(Cb[(size_t)j*pstride + cstride], qy);
        float dz = __fsub_rn(Cb[(size_t)j*pstride + 2*cstride], qz);
        float d = __fadd_rn(__fadd_rn(__fmul_rn(dx,dx), __fmul_rn(dy,dy)), __fmul_rn(dz,dz));
        bool ok = !(d > R2C);
        unsigned m = __ballot_sync(0xffffffffu, ok);
        int pos = cnt + __popc(m & ((1u << lane) - 1u));
        if (ok && pos < NS) buf[wid][pos] = j;
        cnt += __popc(m);
    }
    __syncwarp();
    int first = buf[wid][0];
    int mm = cnt < NS ? cnt : NS;
    int v = (lane < mm) ? buf[wid][lane] : first;
    gi[(size_t)g*NS + lane] = v;
}

// ---------------- gather: build A pre-split bf16 hi/lo, [col][CIN] K-major ----------------
template<int CH>
__global__ void __launch_bounds__(256) k_gatherAB(
    const float* __restrict__ src, int NP,
    const float* __restrict__ sc, const float* __restrict__ bi,
    const int* __restrict__ gi, const int* __restrict__ fpsidx, int S,
    __nv_bfloat16* __restrict__ Ah, __nv_bfloat16* __restrict__ Al)
{
    constexpr int CIN = 2*CH;
    __shared__ float fc[CH];
    __shared__ uint32_t fch[CH/2], fcl[CH/2];
    __shared__ int gix[32];
    int g = blockIdx.x, t = threadIdx.x, wid = t >> 5, lane = t & 31;
    int b = g / S, s = g % S;
    if (t < 32) gix[t] = gi[(size_t)g*NS + t];
    if (t < CH) {
        int ci = fpsidx[(size_t)b*S + s];
        float v = src[((size_t)b*NP + ci)*CH + t]*sc[t] + bi[t];
        fc[t] = fmaxf(v, 0.f);
    }
    __syncthreads();
    if (t < CH/2) split2(fc[2*t], fc[2*t+1], fch[t], fcl[t]);
    __syncthreads();
    for (int k = wid; k < NS; k += 8) {
        size_t row = (size_t)b*NP + gix[k];
        size_t ob = ((size_t)g*NS + k)*CIN;
        for (int cp = lane; cp < CH/2; cp += 32) {
            int c = 2*cp;
            float2 sv = *(const float2*)&src[row*CH + c];
            float v0 = fmaxf(sv.x*sc[c]   + bi[c],   0.f);
            float v1 = fmaxf(sv.y*sc[c+1] + bi[c+1], 0.f);
            uint32_t h, l;
            split2(v0 - fc[c], v1 - fc[c+1], h, l);
            *(uint32_t*)&Ah[ob + c] = h;
            *(uint32_t*)&Al[ob + c] = l;
            *(uint32_t*)&Ah[ob + CH + c] = fch[cp];
            *(uint32_t*)&Al[ob + CH + c] = fcl[cp];
        }
    }
}

// ---------------- mma.sync GEMM ----------------
// PRESPLIT: A supplied as bf16 hi/lo (pure copy fill). else: fp32 + optional BN + in-kernel split.
template<int K, int COUT, bool WRITE_G, bool BN, bool PRESPLIT>
__global__ void __launch_bounds__(256, 2) k_mma(
    const __nv_bfloat16* __restrict__ Wh, const __nv_bfloat16* __restrict__ Wl,
    const float* __restrict__ A32,
    const __nv_bfloat16* __restrict__ Ah, const __nv_bfloat16* __restrict__ Al,
    const float* __restrict__ bnsc, const float* __restrict__ bnbi,
    float* __restrict__ G, float* __restrict__ Fmax,
    double* __restrict__ psum, double* __restrict__ psq,
    int* __restrict__ ctr, int nctas, double invM,
    float* __restrict__ osc, float* __restrict__ obi)
{
    __shared__ __align__(16) __nv_bfloat16 Wht[128*40];
    __shared__ __align__(16) __nv_bfloat16 Wlt[128*40];
    __shared__ __align__(16) __nv_bfloat16 Aht[128*40];
    __shared__ __align__(16) __nv_bfloat16 Alt[128*40];
    __shared__ float sred[128], qred[128];
    __shared__ float scs[256], bis[256];
    __shared__ int lastf;

    int t = threadIdx.x, wid = t >> 5, lane = t & 31;
    int r4 = lane >> 2, q = lane & 3;
    int ntile = blockIdx.x, mtile = blockIdx.y;
    size_t colbase = (size_t)ntile*128;
    int mbase = mtile*128;
    int m0w = (wid & 3)*32, n0w = (wid >> 2)*64;

    for (int i = t; i < 128; i += 256) { sred[i] = 0.f; qred[i] = 0.f; }
    if (BN) for (int i = t; i < K; i += 256) { scs[i] = bnsc[i]; bis[i] = bnbi[i]; }

    float acc[2][8][4];
    #pragma unroll
    for (int im = 0; im < 2; im++)
        #pragma unroll
        for (int in_ = 0; in_ < 8; in_++)
            #pragma unroll
            for (int c = 0; c < 4; c++) acc[im][in_][c] = 0.f;

    constexpr int NCH = K/32;

    uint32_t whtB = (uint32_t)__cvta_generic_to_shared(Wht);
    uint32_t wltB = (uint32_t)__cvta_generic_to_shared(Wlt);
    uint32_t ahtB = (uint32_t)__cvta_generic_to_shared(Aht);
    uint32_t altB = (uint32_t)__cvta_generic_to_shared(Alt);
    uint32_t aOff = (uint32_t)(((m0w + (lane & 15))*40 + (lane >> 4)*8)*2);
    uint32_t bOff = (uint32_t)(((((lane & 7) + ((lane >> 4) << 3)) + n0w)*40 + ((lane >> 3) & 1)*8)*2);

    uint4 pa[4];  // fp32 path
    uint4 pah[2], pal[2];  // presplit path
    if (PRESPLIT) {
        #pragma unroll
        for (int i = 0; i < 2; i++) {
            int idx = t + 256*i, row = idx >> 2, seg = idx & 3;
            pah[i] = *(const uint4*)(Ah + (colbase + row)*(size_t)K + seg*8);
            pal[i] = *(const uint4*)(Al + (colbase + row)*(size_t)K + seg*8);
        }
    } else {
        #pragma unroll
        for (int i = 0; i < 4; i++) {
            int idx = t + 256*i, row = idx >> 3, seg = idx & 7;
            pa[i] = *(const uint4*)(A32 + (colbase + row)*(size_t)K + seg*4);
        }
    }

    #pragma unroll 1
    for (int kc = 0; kc < NCH; kc++) {
        __syncthreads();
        if (PRESPLIT) {
            #pragma unroll
            for (int i = 0; i < 2; i++) {
                int idx = t + 256*i, row = idx >> 2, seg = idx & 3;
                *(uint4*)&Aht[row*40 + seg*8] = pah[i];
                *(uint4*)&Alt[row*40 + seg*8] = pal[i];
            }
        } else {
            #pragma unroll
            for (int i = 0; i < 4; i++) {
                int idx = t + 256*i, row = idx >> 3, seg = idx & 7;
                float4 f = *(float4*)&pa[i];
                if (BN) {
                    int kb = kc*32 + seg*4;
                    f.x = fmaxf(f.x*scs[kb]   + bis[kb],   0.f);
                    f.y = fmaxf(f.y*scs[kb+1] + bis[kb+1], 0.f);
                    f.z = fmaxf(f.z*scs[kb+2] + bis[kb+2], 0.f);
                    f.w = fmaxf(f.w*scs[kb+3] + bis[kb+3], 0.f);
                }
                uint2 hi, lo;
                split4(f.x, f.y, f.z, f.w, hi, lo);
                *(uint2*)&Aht[row*40 + seg*4] = hi;
                *(uint2*)&Alt[row*40 + seg*4] = lo;
            }
        }
        #pragma unroll
        for (int i = 0; i < 2; i++) {
            int idx = t + 256*i, row = idx >> 2, seg = idx & 3;
            *(uint4*)&Wht[row*40 + seg*8] =
                *(const uint4*)(Wh + (size_t)(mbase + row)*K + kc*32 + seg*8);
            *(uint4*)&Wlt[row*40 + seg*8] =
                *(const uint4*)(Wl + (size_t)(mbase + row)*K + kc*32 + seg*8);
        }
        __syncthreads();
        if (kc + 1 < NCH) {
            if (PRESPLIT) {
                #pragma unroll
                for (int i = 0; i < 2; i++) {
                    int idx = t + 256*i, row = idx >> 2, seg = idx & 3;
                    pah[i] = *(const uint4*)(Ah + (colbase + row)*(size_t)K + (kc+1)*32 + seg*8);
                    pal[i] = *(const uint4*)(Al + (colbase + row)*(size_t)K + (kc+1)*32 + seg*8);
                }
            } else {
                #pragma unroll
                for (int i = 0; i < 4; i++) {
                    int idx = t + 256*i, row = idx >> 3, seg = idx & 7;
                    pa[i] = *(const uint4*)(A32 + (colbase + row)*(size_t)K + (kc+1)*32 + seg*4);
                }
            }
        }
        #pragma unroll
        for (int kk = 0; kk < 2; kk++) {
            uint32_t akk = aOff + kk*32;
            uint32_t ah0[4], ah1[4], al0[4], al1[4];
            LDSMX4(ah0, whtB + akk);
            LDSMX4(ah1, whtB + akk + 1280);
            LDSMX4(al0, wltB + akk);
            LDSMX4(al1, wltB + akk + 1280);
            #pragma unroll
            for (int inp = 0; inp < 4; inp++) {
                uint32_t bkk = bOff + (uint32_t)((inp*16*40 + kk*16)*2);
                uint32_t bh[4], bl[4];
                LDSMX4(bh, ahtB + bkk);
                LDSMX4(bl, altB + bkk);
                mma16816(acc[0][2*inp],   ah0, bh[0], bh[1]);
                mma16816(acc[1][2*inp],   ah1, bh[0], bh[1]);
                mma16816(acc[0][2*inp],   ah0, bl[0], bl[1]);
                mma16816(acc[1][2*inp],   ah1, bl[0], bl[1]);
                mma16816(acc[0][2*inp],   al0, bh[0], bh[1]);
                mma16816(acc[1][2*inp],   al1, bh[0], bh[1]);
                mma16816(acc[0][2*inp+1], ah0, bh[2], bh[3]);
                mma16816(acc[1][2*inp+1], ah1, bh[2], bh[3]);
                mma16816(acc[0][2*inp+1], ah0, bl[2], bl[3]);
                mma16816(acc[1][2*inp+1], ah1, bl[2], bl[3]);
                mma16816(acc[0][2*inp+1], al0, bh[2], bh[3]);
                mma16816(acc[1][2*inp+1], al1, bh[2], bh[3]);
            }
        }
    }

    // ---------------- epilogue ----------------
    if (WRITE_G) {
        #pragma unroll
        for (int im = 0; im < 2; im++)
            #pragma unroll
            for (int in_ = 0; in_ < 8; in_++) {
                size_t col = colbase + n0w + in_*8 + q*2;
                int mA = mbase + m0w + im*16 + r4;
                G[col*COUT + mA]       = acc[im][in_][0];
                G[(col+1)*COUT + mA]   = acc[im][in_][1];
                G[col*COUT + mA + 8]   = acc[im][in_][2];
                G[(col+1)*COUT + mA+8] = acc[im][in_][3];
            }
    }
    #pragma unroll
    for (int im = 0; im < 2; im++) {
        float sA = 0.f, sB = 0.f, qA = 0.f, qB = 0.f;
        float mxA[2] = {-3.4e38f, -3.4e38f}, mxB[2] = {-3.4e38f, -3.4e38f};
        #pragma unroll
        for (int in_ = 0; in_ < 8; in_++) {
            int gh = in_ >> 2;
            float v0 = acc[im][in_][0], v1 = acc[im][in_][1];
            float v2 = acc[im][in_][2], v3 = acc[im][in_][3];
            sA += v0 + v1; qA += v0*v0 + v1*v1;
            sB += v2 + v3; qB += v2*v2 + v3*v3;
            mxA[gh] = fmaxf(mxA[gh], fmaxf(v0, v1));
            mxB[gh] = fmaxf(mxB[gh], fmaxf(v2, v3));
        }
        #pragma unroll
        for (int off = 1; off <= 2; off <<= 1) {
            sA += __shfl_xor_sync(0xffffffffu, sA, off);
            qA += __shfl_xor_sync(0xffffffffu, qA, off);
            sB += __shfl_xor_sync(0xffffffffu, sB, off);
            qB += __shfl_xor_sync(0xffffffffu, qB, off);
            #pragma unroll
            for (int gh = 0; gh < 2; gh++) {
                mxA[gh] = fmaxf(mxA[gh], __shfl_xor_sync(0xffffffffu, mxA[gh], off));
                mxB[gh] = fmaxf(mxB[gh], __shfl_xor_sync(0xffffffffu, mxB[gh], off));
            }
        }
        if (q == 0) {
            int lmA = m0w + im*16 + r4, lmB = lmA + 8;
            if (!WRITE_G) {
                size_t g0 = (size_t)ntile*4 + (n0w >> 5);
                Fmax[g0*COUT + mbase + lmA]     = mxA[0];
                Fmax[(g0+1)*COUT + mbase + lmA] = mxA[1];
                Fmax[g0*COUT + mbase + lmB]     = mxB[0];
                Fmax[(g0+1)*COUT + mbase + lmB] = mxB[1];
            }
            atomicAdd(&sred[lmA], sA); atomicAdd(&qred[lmA], qA);
            atomicAdd(&sred[lmB], sB); atomicAdd(&qred[lmB], qB);
        }
    }
    __syncthreads();
    if (t < 128) {
        int slot = (ntile + mtile) & (NSLOT-1);
        atomicAdd(&psum[slot*CMAX + mbase + t], (double)sred[t]);
        atomicAdd(&psq [slot*CMAX + mbase + t], (double)qred[t]);
    }
    __threadfence();
    __syncthreads();
    if (t == 0) lastf = (atomicAdd(ctr, 1) == nctas - 1) ? 1 : 0;
    __syncthreads();
    if (lastf && t < COUT) bn_finalize(psum, psq, osc, obi, t, invM);
}

// ---------------- final output f2 ----------------
__global__ void k_out_f2(const float* __restrict__ Fmax, const float* __restrict__ sc,
                         const float* __restrict__ bi, float* __restrict__ out)
{
    size_t i = (size_t)blockIdx.x*256 + threadIdx.x;
    int s = (int)(i & 255);
    size_t r = i >> 8;
    int c = (int)(r & 255);
    int b = (int)(r >> 8);
    float v = Fmax[((size_t)(b*256 + s))*256 + c]*sc[c] + bi[c];
    out[24576 + i] = fmaxf(v, 0.f);
}

// ---------------- launch ----------------
extern "C" void kernel_launch(void* const* d_in, const int* in_sizes, int n_in,
                              void* d_out, int out_size)
{
    const float* x  = (const float*)d_in[0];
    const float* w1 = (const float*)d_in[1];
    const float* w2 = (const float*)d_in[2];
    const float* wa = (const float*)d_in[3];
    const float* wb = (const float*)d_in[4];
    const float* wc = (const float*)d_in[5];
    const float* wd = (const float*)d_in[6];

    void *pF0, *pF1t, *pnx1, *pfps1, *pgi1, *pF1max, *pnx2, *pfps2, *pgi2, *pF2max;
    void *pAh, *pAl, *pG, *pWh, *pWl, *ppsum, *ppsq, *pscale, *pbias, *pctr;
    cudaGetSymbolAddress(&pF0, g_F0);       cudaGetSymbolAddress(&pF1t, g_F1t);
    cudaGetSymbolAddress(&pnx1, g_nx1);     cudaGetSymbolAddress(&pfps1, g_fps1);
    cudaGetSymbolAddress(&pgi1, g_gi1);     cudaGetSymbolAddress(&pF1max, g_F1max);
    cudaGetSymbolAddress(&pnx2, g_nx2);     cudaGetSymbolAddress(&pfps2, g_fps2);
    cudaGetSymbolAddress(&pgi2, g_gi2);     cudaGetSymbolAddress(&pF2max, g_F2max);
    cudaGetSymbolAddress(&pAh, g_Ah);       cudaGetSymbolAddress(&pAl, g_Al);
    cudaGetSymbolAddress(&pG, g_G);
    cudaGetSymbolAddress(&pWh, g_Wh);       cudaGetSymbolAddress(&pWl, g_Wl);
    cudaGetSymbolAddress(&ppsum, g_psum);   cudaGetSymbolAddress(&ppsq, g_psq);
    cudaGetSymbolAddress(&pscale, g_scale); cudaGetSymbolAddress(&pbias, g_bias);
    cudaGetSymbolAddress(&pctr, g_ctr);

    double* psum = (double*)ppsum;
    double* psq  = (double*)ppsq;
    float* scl = (float*)pscale;
    float* bia = (float*)pbias;
    __nv_bfloat16* Ah = (__nv_bfloat16*)pAh;
    __nv_bfloat16* Al = (__nv_bfloat16*)pAl;
    float* G = (float*)pG;
    __nv_bfloat16* Wh = (__nv_bfloat16*)pWh;
    __nv_bfloat16* Wl = (__nv_bfloat16*)pWl;
    int* ctr = (int*)pctr;

    cudaMemsetAsync(psum, 0, 6*NSLOT*CMAX*sizeof(double), 0);
    cudaMemsetAsync(psq,  0, 6*NSLOT*CMAX*sizeof(double), 0);
    cudaMemsetAsync(ctr,  0, 8*sizeof(int), 0);

    k_wsplit<<<64,256>>>(wa, Wh + 0,      Wl + 0,      16384);
    k_wsplit<<<64,256>>>(wb, Wh + 16384,  Wl + 16384,  16384);
    k_wsplit<<<256,256>>>(wc, Wh + 32768, Wl + 32768,  65536);
    k_wsplit<<<256,256>>>(wd, Wh + 98304, Wl + 98304,  65536);

    // convs (BN finalized in-kernel)
    k_conv1<<<dim3(64,BB), 256>>>(x, w1, (float*)pF0, psum, psq, ctr + 0, scl, bia);
    k_conv2<<<dim3(32,BB), 256>>>((const float*)pF0, w2, scl, bia,
                                  (float*)pF1t, psum + NSLOT*CMAX, psq + NSLOT*CMAX,
                                  ctr + 1, scl + CMAX, bia + CMAX);

    // FPS + ball stage 1
    k_fps<N1,S1><<<BB,256>>>(x, (size_t)3*N1, 1, N1, (int*)pfps1, (float*)pnx1);
    k_ball<<<BB*S1/4,128>>>(x, (size_t)3*N1, 1, N1, N1, (const float*)pnx1, S1, (int*)pgi1);

    // sg1
    k_gatherAB<64><<<BB*S1, 256>>>((const float*)pF1t, N1, scl + CMAX, bia + CMAX,
                                   (const int*)pgi1, (const int*)pfps1, S1, Ah, Al);
    k_mma<128,128,true,false,true><<<dim3(NT1/128,1), 256>>>(Wh + 0, Wl + 0,
        nullptr, Ah, Al, nullptr, nullptr,
        G, nullptr, psum + 2*NSLOT*CMAX, psq + 2*NSLOT*CMAX,
        ctr + 2, NT1/128, 1.0/((double)NT1), scl + 2*CMAX, bia + 2*CMAX);
    k_mma<128,128,false,true,false><<<dim3(NT1/128,1), 256>>>(Wh + 16384, Wl + 16384,
        G, nullptr, nullptr, scl + 2*CMAX, bia + 2*CMAX,
        nullptr, (float*)pF1max, psum + 3*NSLOT*CMAX, psq + 3*NSLOT*CMAX,
        ctr + 3, NT1/128, 1.0/((double)NT1), scl + 3*CMAX, bia + 3*CMAX);

    // FPS + ball stage 2
    k_fps<S1,S2><<<BB,256>>>((const float*)pnx1, (size_t)S1*3, 3, 1, (int*)pfps2, (float*)pnx2);
    k_ball<<<BB*S2/4,128>>>((const float*)pnx1, (size_t)S1*3, 3, 1, S1, (const float*)pnx2, S2, (int*)pgi2);

    // sg2
    k_gatherAB<128><<<BB*S2, 256>>>((const float*)pF1max, S1, scl + 3*CMAX, bia + 3*CMAX,
                                    (const int*)pgi2, (const int*)pfps2, S2, Ah, Al);
    k_mma<256,256,true,false,true><<<dim3(NT2/128,2), 256>>>(Wh + 32768, Wl + 32768,
        nullptr, Ah, Al, nullptr, nullptr,
        G, nullptr, psum + 4*NSLOT*CMAX, psq + 4*NSLOT*CMAX,
        ctr + 4, (NT2/128)*2, 1.0/((double)NT2), scl + 4*CMAX, bia + 4*CMAX);
    k_mma<256,256,false,true,false><<<dim3(NT2/128,2), 256>>>(Wh + 98304, Wl + 98304,
        G, nullptr, nullptr, scl + 4*CMAX, bia + 4*CMAX,
        nullptr, (float*)pF2max, psum + 5*NSLOT*CMAX, psq + 5*NSLOT*CMAX,
        ctr + 5, (NT2/128)*2, 1.0/((double)NT2), scl + 5*CMAX, bia + 5*CMAX);

    // outputs
    cudaMemcpyAsync(d_out, pnx2, (size_t)BB*S2*3*sizeof(float), cudaMemcpyDeviceToDevice, 0);
    k_out_f2<<<(BB*256*256)/256, 256>>>((const float*)pF2max, scl + 5*CMAX, bia + 5*CMAX, (float*)d_out);
}